// round 5
// baseline (speedup 1.0000x reference)
#include <cuda_runtime.h>
#include <cuda_bf16.h>
#include <math.h>

#define NNODES 32768
#define NEDGES 524288
#define NB     32
#define NPG    1024
#define CH     128
#define CIN    64

// ---------------- device scratch ----------------
__device__ int   g_deg[NNODES];
__device__ int   g_off[NNODES];
__device__ int   g_cur[NNODES];
__device__ int   g_total;
__device__ int   g_srcbuf[NEDGES];
__device__ float g_dinv[NNODES];

__device__ float g_aggx[NNODES * CIN];
__device__ float g_lin[NNODES * CH];
__device__ float g_y  [NNODES * CH];
__device__ float g_h  [NNODES * CH];
__device__ float g_s  [NNODES * CH];
__device__ float g_t  [NNODES * CH];

__device__ float g_xpart[4 * NB * CH * CH];
__device__ float g_apart[4 * NB * CH * CH];
__device__ float g_x2  [NB * CH * CH];
__device__ float g_A2  [NB * CH * CH];
__device__ float g_An  [NB * CH * CH];
__device__ float g_h2  [NB * CH * CH];
__device__ float g_tmp2[NB * CH * CH];
__device__ float g_y2  [NB * CH * CH];

__device__ float g_sum[CH], g_ss[CH];

// packed fp32x2 FMA: d = a*b + d, lanewise on 2 floats in a 64-bit reg.
// Base sm_100+ PTX (NOT an 'a'-variant feature like tcgen05).
__device__ __forceinline__ void ffma2(unsigned long long& d, unsigned long long a, unsigned long long b) {
    asm("fma.rn.f32x2 %0, %1, %2, %0;" : "+l"(d) : "l"(a), "l"(b));
}
__device__ __forceinline__ unsigned long long dup_f32(float v) {
    unsigned long long r;
    asm("mov.b64 %0, {%1, %1};" : "=l"(r) : "f"(v));
    return r;
}

// ---------------- utility ----------------
__global__ void k_zero_deg() {
    int i = blockIdx.x * 256 + threadIdx.x;
    if (i < NNODES) g_deg[i] = 0;
    if (i == 0) g_total = 0;
}
__global__ void k_zero_f(float* p, int n) {
    int i = blockIdx.x * 256 + threadIdx.x;
    if (i < n) p[i] = 0.f;
}

// ---------------- graph structure ----------------
__global__ void k_deg(const int* __restrict__ ei) {
    int e = blockIdx.x * 256 + threadIdx.x;
    if (e < NEDGES) atomicAdd(&g_deg[ei[NEDGES + e]], 1);
}

__global__ void k_alloc() {
    int t = threadIdx.x;
    int node = blockIdx.x * 1024 + t;
    int lane = t & 31;
    int deg = g_deg[node];
    int incl = deg;
#pragma unroll
    for (int d = 1; d < 32; d <<= 1) {
        int v = __shfl_up_sync(0xffffffffu, incl, d);
        if (lane >= d) incl += v;
    }
    int tot = __shfl_sync(0xffffffffu, incl, 31);
    int base = 0;
    if (lane == 31) base = atomicAdd(&g_total, tot);
    base = __shfl_sync(0xffffffffu, base, 31);
    int off = base + incl - deg;
    g_off[node] = off;
    g_cur[node] = off;
    g_dinv[node] = rsqrtf((float)deg + 1.0f);
}

__global__ void k_fill(const int* __restrict__ ei) {
    int e = blockIdx.x * 256 + threadIdx.x;
    if (e < NEDGES) {
        int d = ei[NEDGES + e];
        int p = atomicAdd(&g_cur[d], 1);
        g_srcbuf[p] = ei[e];
    }
}

// ---------------- big SGEMM: 128x128 tile, 8x8 micro, 256 thr, FFMA2 inner ----------------
// TRANSA=false: C[M,128] = A[M,lda] @ B[K,128]; TRANSA=true: C[128,128] = A[K,128]^T @ B[K,128]
template <bool TRANSA>
__global__ __launch_bounds__(256) void k_gemm(
    const float* __restrict__ A, const float* __restrict__ B,
    const float* __restrict__ bias, float* __restrict__ C,
    int lda, int kChunk,
    long long sA, long long sB, long long sC, long long sCy, int zeroStats)
{
    __shared__ __align__(16) float As[8 * 132];
    __shared__ __align__(16) float Bs[8 * 128];
    int t = threadIdx.x;
    if (zeroStats && blockIdx.x == 0 && blockIdx.y == 0 && blockIdx.z == 0 && t < 128) {
        g_sum[t] = 0.f; g_ss[t] = 0.f;
    }
    A += (long long)blockIdx.z * sA;
    B += (long long)blockIdx.z * sB;
    C += (long long)blockIdx.z * sC + (long long)blockIdx.y * sCy;
    int m0 = blockIdx.x * 128;
    int tx = t & 15, ty = t >> 4;
    unsigned long long acc2[8][4];
#pragma unroll
    for (int i = 0; i < 8; i++)
#pragma unroll
        for (int j = 0; j < 4; j++) acc2[i][j] = 0ull;

    int kStart = blockIdx.y * kChunk;
    for (int k0 = kStart; k0 < kStart + kChunk; k0 += 8) {
        if (TRANSA) {
            int kk = t >> 5;
            int mq = (t & 31) << 2;
            float4 v = *reinterpret_cast<const float4*>(&A[(long long)(k0 + kk) * 128 + mq]);
            *reinterpret_cast<float4*>(&As[kk * 132 + mq]) = v;
        } else {
            int r  = t >> 1;
            int kq = (t & 1) << 2;
            float4 v = *reinterpret_cast<const float4*>(&A[(long long)(m0 + r) * lda + k0 + kq]);
            As[(kq + 0) * 132 + r] = v.x; As[(kq + 1) * 132 + r] = v.y;
            As[(kq + 2) * 132 + r] = v.z; As[(kq + 3) * 132 + r] = v.w;
        }
        {
            int kk = t >> 5;
            int nq = (t & 31) << 2;
            float4 v = *reinterpret_cast<const float4*>(&B[(long long)(k0 + kk) * 128 + nq]);
            *reinterpret_cast<float4*>(&Bs[kk * 128 + nq]) = v;
        }
        __syncthreads();
#pragma unroll
        for (int kk = 0; kk < 8; kk++) {
            float a[8];
            unsigned long long b2[4];
            *(float4*)&a[0] = *(const float4*)&As[kk * 132 + ty * 8];
            *(float4*)&a[4] = *(const float4*)&As[kk * 132 + ty * 8 + 4];
            const unsigned long long* Bp =
                reinterpret_cast<const unsigned long long*>(&Bs[kk * 128 + tx * 8]);
            b2[0] = Bp[0]; b2[1] = Bp[1]; b2[2] = Bp[2]; b2[3] = Bp[3];
#pragma unroll
            for (int i = 0; i < 8; i++) {
                unsigned long long ad = dup_f32(a[i]);
#pragma unroll
                for (int j = 0; j < 4; j++) ffma2(acc2[i][j], ad, b2[j]);
            }
        }
        __syncthreads();
    }

#pragma unroll
    for (int i = 0; i < 8; i++) {
        long long row = m0 + ty * 8 + i;
        const float* af = reinterpret_cast<const float*>(&acc2[i][0]);
#pragma unroll
        for (int j = 0; j < 8; j++) {
            int col = tx * 8 + j;
            float v = af[j];
            if (bias) v += bias[col];
            C[row * 128 + col] = v;
        }
    }
}

// ---------------- small SGEMM: 64x64 tile, 4x4 micro, 256 thr, FFMA2 inner ----------------
__global__ __launch_bounds__(256) void k_gemm64(
    const float* __restrict__ A, const float* __restrict__ B,
    const float* __restrict__ bias, float* __restrict__ C,
    int K, long long sA, long long sB, long long sC, int zeroStats)
{
    __shared__ __align__(16) float As[16 * 68];
    __shared__ __align__(16) float Bs[16 * 64];
    int t = threadIdx.x;
    if (zeroStats && blockIdx.x == 0 && blockIdx.y == 0 && blockIdx.z == 0 && t < 128) {
        g_sum[t] = 0.f; g_ss[t] = 0.f;
    }
    A += (long long)blockIdx.z * sA;
    B += (long long)blockIdx.z * sB;
    C += (long long)blockIdx.z * sC;
    int m0 = blockIdx.x * 64;
    int n0 = blockIdx.y * 64;
    int tx = t & 15, ty = t >> 4;
    unsigned long long acc2[4][2];
#pragma unroll
    for (int i = 0; i < 4; i++) { acc2[i][0] = 0ull; acc2[i][1] = 0ull; }

    for (int k0 = 0; k0 < K; k0 += 16) {
        {
            int r  = t >> 2;
            int kq = (t & 3) << 2;
            float4 v = *reinterpret_cast<const float4*>(&A[(long long)(m0 + r) * 128 + k0 + kq]);
            As[(kq + 0) * 68 + r] = v.x; As[(kq + 1) * 68 + r] = v.y;
            As[(kq + 2) * 68 + r] = v.z; As[(kq + 3) * 68 + r] = v.w;
        }
        {
            int kk = t >> 4;
            int nq = (t & 15) << 2;
            float4 v = *reinterpret_cast<const float4*>(&B[(long long)(k0 + kk) * 128 + n0 + nq]);
            *reinterpret_cast<float4*>(&Bs[kk * 64 + nq]) = v;
        }
        __syncthreads();
#pragma unroll
        for (int kk = 0; kk < 16; kk++) {
            float a[4];
            unsigned long long b2[2];
#pragma unroll
            for (int i = 0; i < 4; i++) a[i] = As[kk * 68 + ty * 4 + i];
            const unsigned long long* Bp =
                reinterpret_cast<const unsigned long long*>(&Bs[kk * 64 + tx * 4]);
            b2[0] = Bp[0]; b2[1] = Bp[1];
#pragma unroll
            for (int i = 0; i < 4; i++) {
                unsigned long long ad = dup_f32(a[i]);
                ffma2(acc2[i][0], ad, b2[0]);
                ffma2(acc2[i][1], ad, b2[1]);
            }
        }
        __syncthreads();
    }
#pragma unroll
    for (int i = 0; i < 4; i++) {
        long long row = m0 + ty * 4 + i;
        const float* af = reinterpret_cast<const float*>(&acc2[i][0]);
#pragma unroll
        for (int j = 0; j < 4; j++) {
            int col = n0 + tx * 4 + j;
            float v = af[j];
            if (bias) v += bias[col];
            C[row * 128 + col] = v;
        }
    }
}

// ---------------- sparse aggregation (CSR gather), multi-node blocks ----------------
template <int CHN, bool SOFTMAX, bool ZERO>
__global__ __launch_bounds__(256) void k_agg_gcn(
    const float* __restrict__ in, const float* __restrict__ bias, float* __restrict__ out)
{
    int t = threadIdx.x;
    if (ZERO && blockIdx.x == 0 && t < 128) { g_sum[t] = 0.f; g_ss[t] = 0.f; }
    const int NPB = 256 / CHN;
    int local = t / CHN;
    int c = t % CHN;
    int i = blockIdx.x * NPB + local;
    float di = g_dinv[i];
    float acc = di * in[(size_t)i * CHN + c];
    int e = g_off[i];
    int e1 = e + g_deg[i];
    for (; e + 4 <= e1; e += 4) {
        int s0 = g_srcbuf[e], s1 = g_srcbuf[e + 1], s2 = g_srcbuf[e + 2], s3 = g_srcbuf[e + 3];
        float d0 = g_dinv[s0], d1 = g_dinv[s1], d2 = g_dinv[s2], d3 = g_dinv[s3];
        float h0 = in[(size_t)s0 * CHN + c];
        float h1 = in[(size_t)s1 * CHN + c];
        float h2 = in[(size_t)s2 * CHN + c];
        float h3 = in[(size_t)s3 * CHN + c];
        acc += d0 * h0 + d1 * h1 + d2 * h2 + d3 * h3;
    }
    for (; e < e1; e++) {
        int s = g_srcbuf[e];
        acc += g_dinv[s] * in[(size_t)s * CHN + c];
    }
    float v = di * acc + (bias ? bias[c] : 0.f);
    if (!SOFTMAX) {
        out[(size_t)i * CHN + c] = v;
    } else {
        __shared__ float red[256];
        red[t] = v; __syncthreads();
#pragma unroll
        for (int s = 64; s; s >>= 1) {
            if (c < s) red[t] = fmaxf(red[t], red[t + s]);
            __syncthreads();
        }
        float mx = red[local * 128];
        __syncthreads();
        float ex = expf(v - mx);
        red[t] = ex; __syncthreads();
#pragma unroll
        for (int s = 64; s; s >>= 1) {
            if (c < s) red[t] += red[t + s];
            __syncthreads();
        }
        out[(size_t)i * CHN + c] = ex / red[local * 128];
    }
}

__global__ __launch_bounds__(256) void k_agg_plain(
    const float* __restrict__ in, float* __restrict__ out)
{
    int t = threadIdx.x;
    int local = t >> 7;
    int c = t & 127;
    int i = blockIdx.x * 2 + local;
    float acc = 0.f;
    int e = g_off[i];
    int e1 = e + g_deg[i];
    for (; e + 4 <= e1; e += 4) {
        int s0 = g_srcbuf[e], s1 = g_srcbuf[e + 1], s2 = g_srcbuf[e + 2], s3 = g_srcbuf[e + 3];
        acc += in[(size_t)s0 * CH + c] + in[(size_t)s1 * CH + c]
             + in[(size_t)s2 * CH + c] + in[(size_t)s3 * CH + c];
    }
    for (; e < e1; e++) acc += in[(size_t)g_srcbuf[e] * CH + c];
    out[(size_t)i * CH + c] = acc;
}

// ---------------- batch-norm stats + apply (fin inlined) ----------------
__global__ __launch_bounds__(128) void k_bnstats(const float* __restrict__ x, int nrows) {
    int c = threadIdx.x;
    float s = 0.f, q = 0.f;
    for (int r = blockIdx.x; r < nrows; r += gridDim.x) {
        float v = x[(long long)r * CH + c];
        s += v; q += v * v;
    }
    atomicAdd(&g_sum[c], s);
    atomicAdd(&g_ss[c], q);
}

__global__ __launch_bounds__(256) void k_bnapply4(
    const float4* __restrict__ x, const float4* __restrict__ res, float4* __restrict__ out,
    int n4, const float* __restrict__ gw, const float* __restrict__ be, float inv_n)
{
    __shared__ float sA[128], sB[128];
    int t = threadIdx.x;
    if (t < 128) {
        float m = g_sum[t] * inv_n;
        float v = g_ss[t] * inv_n - m * m;
        float sc = gw[t] * rsqrtf(v + 1e-5f);
        sA[t] = sc;
        sB[t] = be[t] - sc * m;
    }
    __syncthreads();
    int i = blockIdx.x * 256 + t;
    if (i >= n4) return;
    int c0 = (i & 31) << 2;
    float4 xv = x[i];
    float4 o;
    float y;
    y = sA[c0 + 0] * xv.x + sB[c0 + 0]; o.x = y / (1.f + __expf(-y));
    y = sA[c0 + 1] * xv.y + sB[c0 + 1]; o.y = y / (1.f + __expf(-y));
    y = sA[c0 + 2] * xv.z + sB[c0 + 2]; o.z = y / (1.f + __expf(-y));
    y = sA[c0 + 3] * xv.w + sB[c0 + 3]; o.w = y / (1.f + __expf(-y));
    if (res) {
        float4 r = res[i];
        o.x += r.x; o.y += r.y; o.z += r.z; o.w += r.w;
    }
    out[i] = o;
}

// ---------------- partial reduce + dinv2 + An (per batch) ----------------
__global__ __launch_bounds__(256) void k_reduce_an() {
    int b = blockIdx.x;
    int t = threadIdx.x;
    const int PS = NB * CH * CH;
    const int BO = b * CH * CH;
    __shared__ float sd[128];
    for (int idx = t; idx < CH * CH; idx += 256) {
        float s = g_xpart[0 * PS + BO + idx] + g_xpart[1 * PS + BO + idx]
                + g_xpart[2 * PS + BO + idx] + g_xpart[3 * PS + BO + idx];
        g_x2[BO + idx] = s;
    }
    int w = t >> 5, lane = t & 31;
    for (int r = w; r < 128; r += 8) {
        float rsum = 0.f;
#pragma unroll
        for (int q = 0; q < 4; q++) {
            int idx = r * 128 + lane + q * 32;
            float s = g_apart[0 * PS + BO + idx] + g_apart[1 * PS + BO + idx]
                    + g_apart[2 * PS + BO + idx] + g_apart[3 * PS + BO + idx];
            g_A2[BO + idx] = s;
            rsum += s;
        }
#pragma unroll
        for (int o = 16; o; o >>= 1) rsum += __shfl_down_sync(0xffffffffu, rsum, o);
        if (lane == 0) sd[r] = rsqrtf(rsum + 1.0f);
    }
    __syncthreads();
    for (int idx = t; idx < CH * CH; idx += 256) {
        int i = idx >> 7, j = idx & 127;
        float v = g_A2[BO + idx] + (i == j ? 1.f : 0.f);
        g_An[BO + idx] = sd[i] * v * sd[j];
    }
}

// ---------------- pooled column-mean + linear head + log_softmax ----------------
__global__ __launch_bounds__(128) void k_head(
    const float* __restrict__ wl, const float* __restrict__ bl, float* __restrict__ out, int out_size)
{
    int b = blockIdx.x;
    int t = threadIdx.x;
    __shared__ float gv[128];
    __shared__ float lg[10];
    __shared__ float s_lse;
    float s = 0.f;
    for (int n = 0; n < 128; n++) s += g_h2[((long long)b * 128 + n) * 128 + t];
    gv[t] = s * (1.f / 32.f);
    __syncthreads();
    if (t < 10) {
        float a = bl[t];
        for (int k = 0; k < 128; k++) a += gv[k] * wl[k * 10 + t];
        lg[t] = a;
    }
    __syncthreads();
    if (t == 0) {
        float mx = -1e30f;
        for (int j = 0; j < 10; j++) mx = fmaxf(mx, lg[j]);
        float se = 0.f;
        for (int j = 0; j < 10; j++) se += expf(lg[j] - mx);
        s_lse = mx + logf(se);
    }
    __syncthreads();
    if (t < 10) {
        int o = b * 10 + t;
        if (o < out_size) out[o] = lg[t] - s_lse;
    }
}

// ---------------- host orchestration ----------------
extern "C" void kernel_launch(void* const* d_in, const int* in_sizes, int n_in,
                              void* d_out, int out_size) {
    const float* x    = (const float*)d_in[0];
    const int*   ei   = (const int*)  d_in[1];
    const float* w1a  = (const float*)d_in[4];
    const float* b1a  = (const float*)d_in[5];
    const float* g1a  = (const float*)d_in[6];
    const float* be1a = (const float*)d_in[7];
    const float* w1b  = (const float*)d_in[8];
    const float* b1b  = (const float*)d_in[9];
    const float* g1b  = (const float*)d_in[10];
    const float* be1b = (const float*)d_in[11];
    const float* wp1  = (const float*)d_in[12];
    const float* bp1  = (const float*)d_in[13];
    const float* w2a  = (const float*)d_in[14];
    const float* b2a  = (const float*)d_in[15];
    const float* g2a  = (const float*)d_in[16];
    const float* be2a = (const float*)d_in[17];
    const float* w2b  = (const float*)d_in[18];
    const float* b2b  = (const float*)d_in[19];
    const float* g2b  = (const float*)d_in[20];
    const float* be2b = (const float*)d_in[21];
    // d_in[22]=wp2, d_in[23]=bp2 dead (softmax rows sum to 1)
    const float* wl   = (const float*)d_in[24];
    const float* bl   = (const float*)d_in[25];
    float* outp = (float*)d_out;
    (void)n_in; (void)in_sizes;

    float *p_aggx, *p_lin, *p_y, *p_h, *p_s, *p_t;
    float *p_xpart, *p_apart, *p_x2, *p_An, *p_h2, *p_tmp2, *p_y2;
    cudaGetSymbolAddress((void**)&p_aggx,  g_aggx);
    cudaGetSymbolAddress((void**)&p_lin,   g_lin);
    cudaGetSymbolAddress((void**)&p_y,     g_y);
    cudaGetSymbolAddress((void**)&p_h,     g_h);
    cudaGetSymbolAddress((void**)&p_s,     g_s);
    cudaGetSymbolAddress((void**)&p_t,     g_t);
    cudaGetSymbolAddress((void**)&p_xpart, g_xpart);
    cudaGetSymbolAddress((void**)&p_apart, g_apart);
    cudaGetSymbolAddress((void**)&p_x2,    g_x2);
    cudaGetSymbolAddress((void**)&p_An,    g_An);
    cudaGetSymbolAddress((void**)&p_h2,    g_h2);
    cudaGetSymbolAddress((void**)&p_tmp2,  g_tmp2);
    cudaGetSymbolAddress((void**)&p_y2,    g_y2);

    const int NC = NNODES * CH;     // 4194304
    const int S2 = NB * CH * CH;    // 524288

    // --- graph structure ---
    k_zero_deg<<<NNODES / 256, 256>>>();
    k_deg  <<<NEDGES / 256, 256>>>(ei);
    k_alloc<<<NNODES / 1024, 1024>>>();
    k_fill <<<NEDGES / 256, 256>>>(ei);

    // --- stack 1, layer a: agg(x) first (64ch), then GEMM 64->128 with bias ---
    k_agg_gcn<64, false, false><<<NNODES / 4, 256>>>(x, nullptr, p_aggx);
    k_gemm<false><<<dim3(256, 1, 1), 256>>>(p_aggx, w1a, b1a, p_y, 64, 64, 0, 0, 0, 0, 1);
    k_bnstats<<<256, 128>>>(p_y, NNODES);
    k_bnapply4<<<NC / 1024, 256>>>((const float4*)p_y, nullptr, (float4*)p_h, NC / 4, g1a, be1a, 1.f / NNODES);

    // --- stack 1, layer b (residual) ---
    k_gemm<false><<<dim3(256, 1, 1), 256>>>(p_h, w1b, nullptr, p_lin, 128, 128, 0, 0, 0, 0, 0);
    k_agg_gcn<128, false, true><<<NNODES / 2, 256>>>(p_lin, b1b, p_y);
    k_bnstats<<<256, 128>>>(p_y, NNODES);
    k_bnapply4<<<NC / 1024, 256>>>((const float4*)p_y, (const float4*)p_h, (float4*)p_h, NC / 4, g1b, be1b, 1.f / NNODES);

    // --- pooling 1: s = softmax(gcn(h, wp1)) fused; t = A s ---
    k_gemm<false><<<dim3(256, 1, 1), 256>>>(p_h, wp1, nullptr, p_lin, 128, 128, 0, 0, 0, 0, 0);
    k_agg_gcn<128, true, false><<<NNODES / 2, 256>>>(p_lin, bp1, p_s);
    k_agg_plain<<<NNODES / 2, 256>>>(p_s, p_t);

    // --- pooled einsums: K-split x4 into partial buffers (no atomics) ---
    k_gemm<true><<<dim3(1, 4, NB), 256>>>(p_s, p_h, nullptr, p_xpart, 128, 256,
                                          (long long)NPG * CH, (long long)NPG * CH,
                                          (long long)CH * CH, (long long)NB * CH * CH, 0);
    k_gemm<true><<<dim3(1, 4, NB), 256>>>(p_s, p_t, nullptr, p_apart, 128, 256,
                                          (long long)NPG * CH, (long long)NPG * CH,
                                          (long long)CH * CH, (long long)NB * CH * CH, 0);
    k_reduce_an<<<NB, 256>>>();

    // --- stack 2, layer a ---
    k_gemm64<<<dim3(64, 2, 1), 256>>>(p_x2, w2a, nullptr, p_tmp2, 128, 0, 0, 0, 0);
    k_gemm64<<<dim3(2, 2, NB), 256>>>(p_An, p_tmp2, b2a, p_y2, 128, 16384, 16384, 16384, 1);
    k_bnstats<<<64, 128>>>(p_y2, NB * CH);
    k_bnapply4<<<S2 / 1024, 256>>>((const float4*)p_y2, nullptr, (float4*)p_h2, S2 / 4, g2a, be2a, 1.f / (NB * CH));

    // --- stack 2, layer b (residual) ---
    k_gemm64<<<dim3(64, 2, 1), 256>>>(p_h2, w2b, nullptr, p_tmp2, 128, 0, 0, 0, 0);
    k_gemm64<<<dim3(2, 2, NB), 256>>>(p_An, p_tmp2, b2b, p_y2, 128, 16384, 16384, 16384, 1);
    k_bnstats<<<64, 128>>>(p_y2, NB * CH);
    k_bnapply4<<<S2 / 1024, 256>>>((const float4*)p_y2, (const float4*)p_h2, (float4*)p_h2, S2 / 4, g2b, be2b, 1.f / (NB * CH));

    // --- head ---
    k_head<<<NB, 128>>>(wl, bl, outp, out_size);

    if (out_size > NB * 10) {
        int tail = out_size - NB * 10;
        k_zero_f<<<(tail + 255) / 256, 256>>>(outp + NB * 10, tail);
    }
}

// round 6
// speedup vs baseline: 1.4590x; 1.4590x over previous
#include <cuda_runtime.h>
#include <math.h>
#include <stdint.h>

#define NNODES 32768
#define NEDGES 524288
#define NB     32
#define NPG    1024
#define CH     128
#define CIN    64

// ================= helpers =================
__device__ __forceinline__ uint32_t smem_u32(const void* p) {
    uint32_t a;
    asm("{ .reg .u64 t; cvta.to.shared.u64 t, %1; cvt.u32.u64 %0, t; }" : "=r"(a) : "l"(p));
    return a;
}
__device__ __forceinline__ void ffma2(unsigned long long& d, unsigned long long a, unsigned long long b) {
    asm("fma.rn.f32x2 %0, %1, %2, %0;" : "+l"(d) : "l"(a), "l"(b));
}
__device__ __forceinline__ unsigned long long dup_f32(float v) {
    unsigned long long r;
    asm("mov.b64 %0, {%1, %1};" : "=l"(r) : "f"(v));
    return r;
}
__device__ __forceinline__ float2 u2f(unsigned long long v) {
    float2 f;
    asm("mov.b64 {%0, %1}, %2;" : "=f"(f.x), "=f"(f.y) : "l"(v));
    return f;
}
#define CP_ASYNC16(dst, src) asm volatile("cp.async.ca.shared.global [%0], [%1], 16;" :: "r"(dst), "l"(src))
#define CP_COMMIT()          asm volatile("cp.async.commit_group;" ::: "memory")
#define CP_WAIT(n)           asm volatile("cp.async.wait_group %0;" :: "n"(n) : "memory")

// ================= device scratch =================
__device__ int   g_deg[NNODES];
__device__ int   g_off[NNODES];
__device__ int   g_cur[NNODES];
__device__ int   g_total;
__device__ int   g_srcbuf[NEDGES];
__device__ float g_dinv[NNODES];

__device__ float g_lin[NNODES * CH];
__device__ float g_y  [NNODES * CH];
__device__ float g_h  [NNODES * CH];
__device__ float g_s  [NNODES * CH];
__device__ float g_t  [NNODES * CH];
__device__ float g_axT[CIN * NNODES];
__device__ float g_hT [CH * NNODES];

__device__ float g_xpart[8 * NB * CH * CH];
__device__ float g_apart[8 * NB * CH * CH];
__device__ float g_x2  [NB * CH * CH];
__device__ float g_A2  [NB * CH * CH];
__device__ float g_An  [NB * CH * CH];

__device__ float g_sumA[CH], g_ssA[CH], g_sumB[CH], g_ssB[CH];
__device__ float g_s2a[CH], g_q2a[CH], g_s2b[CH], g_q2b[CH];
__device__ int   g_bar;

// ================= graph structure =================
__global__ void k_zero_deg() {
    int i = blockIdx.x * 256 + threadIdx.x;
    if (i < NNODES) g_deg[i] = 0;
    if (i < 128) { g_sumA[i] = 0.f; g_ssA[i] = 0.f; g_sumB[i] = 0.f; g_ssB[i] = 0.f; }
    if (i == 0) g_total = 0;
}
__global__ void k_deg(const int* __restrict__ ei) {
    int e = blockIdx.x * 256 + threadIdx.x;
    if (e < NEDGES) atomicAdd(&g_deg[ei[NEDGES + e]], 1);
}
__global__ void k_alloc() {
    int t = threadIdx.x;
    int node = blockIdx.x * 1024 + t;
    int lane = t & 31;
    int deg = g_deg[node];
    int incl = deg;
#pragma unroll
    for (int d = 1; d < 32; d <<= 1) {
        int v = __shfl_up_sync(0xffffffffu, incl, d);
        if (lane >= d) incl += v;
    }
    int tot = __shfl_sync(0xffffffffu, incl, 31);
    int base = 0;
    if (lane == 31) base = atomicAdd(&g_total, tot);
    base = __shfl_sync(0xffffffffu, base, 31);
    int off = base + incl - deg;
    g_off[node] = off;
    g_cur[node] = off;
    g_dinv[node] = rsqrtf((float)deg + 1.0f);
}
__global__ void k_fill(const int* __restrict__ ei) {
    int e = blockIdx.x * 256 + threadIdx.x;
    if (e < NEDGES) {
        int d = ei[NEDGES + e];
        int p = atomicAdd(&g_cur[d], 1);
        g_srcbuf[p] = ei[e];
    }
}

// ================= unified cp.async double-buffered GEMM =================
// C[m0+m, j] = sum_k AT[k, m0+m] * B[k, j] (+bias); AT row stride = strideA.
template<bool POOLED>
__global__ __launch_bounds__(256) void k_gemmu(
    const float* __restrict__ A, const float* __restrict__ B1, const float* __restrict__ B2,
    const float* __restrict__ bias, float* __restrict__ C1, float* __restrict__ C2,
    long long strideA, int K, int doStats)
{
    __shared__ __align__(16) float As[2][1024];
    __shared__ __align__(16) float Bs[2][1024];
    int t = threadIdx.x;
    int tx = t & 15, ty = t >> 4;
    const float *Ab, *Bb;
    float* Cb;
    if (POOLED) {
        int g = blockIdx.z;
        int half = blockIdx.y >> 3, chunk = blockIdx.y & 7;
        long long rbase = ((long long)g * 1024 + (long long)chunk * 128) * 128;
        Ab = A + rbase;
        Bb = (half ? B2 : B1) + rbase;
        Cb = (half ? C2 : C1) + (long long)(chunk * NB + g) * (CH * CH);
    } else {
        Ab = A + (long long)blockIdx.x * 128;
        Bb = B1;
        Cb = C1 + (long long)blockIdx.x * 128 * 128;
    }
    uint32_t sA0 = smem_u32(&As[0][0]), sA1 = smem_u32(&As[1][0]);
    uint32_t sB0 = smem_u32(&Bs[0][0]), sB1 = smem_u32(&Bs[1][0]);
    int r = t >> 5, sg = (t & 31) * 4;
    uint32_t dA = (uint32_t)((r * 128 + sg) * 4);

    CP_ASYNC16(sA0 + dA, Ab + (long long)r * strideA + sg);
    CP_ASYNC16(sB0 + dA, Bb + (long long)r * 128 + sg);
    CP_COMMIT();

    unsigned long long acc2[8][4];
#pragma unroll
    for (int i = 0; i < 8; i++)
#pragma unroll
        for (int j = 0; j < 4; j++) acc2[i][j] = 0ull;

    int NT = K >> 3;
    for (int kt = 0; kt < NT; kt++) {
        int cur = kt & 1;
        if (kt + 1 < NT) {
            int k0 = (kt + 1) << 3;
            uint32_t an = (kt & 1) ? sA0 : sA1;
            uint32_t bn = (kt & 1) ? sB0 : sB1;
            CP_ASYNC16(an + dA, Ab + (long long)(k0 + r) * strideA + sg);
            CP_ASYNC16(bn + dA, Bb + (long long)(k0 + r) * 128 + sg);
            CP_COMMIT();
            CP_WAIT(1);
        } else {
            CP_WAIT(0);
        }
        __syncthreads();
        const float* Ac = As[cur];
        const float* Bc = Bs[cur];
#pragma unroll
        for (int kk = 0; kk < 8; kk++) {
            float a[8];
            *(float4*)&a[0] = *(const float4*)&Ac[kk * 128 + ty * 8];
            *(float4*)&a[4] = *(const float4*)&Ac[kk * 128 + ty * 8 + 4];
            const unsigned long long* Bp =
                reinterpret_cast<const unsigned long long*>(&Bc[kk * 128 + tx * 8]);
            unsigned long long b0 = Bp[0], b1 = Bp[1], b2 = Bp[2], b3 = Bp[3];
#pragma unroll
            for (int i = 0; i < 8; i++) {
                unsigned long long ad = dup_f32(a[i]);
                ffma2(acc2[i][0], ad, b0);
                ffma2(acc2[i][1], ad, b1);
                ffma2(acc2[i][2], ad, b2);
                ffma2(acc2[i][3], ad, b3);
            }
        }
        __syncthreads();
    }

    float cs[8], cq[8];
#pragma unroll
    for (int j = 0; j < 8; j++) { cs[j] = 0.f; cq[j] = 0.f; }
#pragma unroll
    for (int i = 0; i < 8; i++) {
        int row = ty * 8 + i;
        float v[8];
#pragma unroll
        for (int j = 0; j < 4; j++) {
            float2 p = u2f(acc2[i][j]);
            v[2 * j] = p.x; v[2 * j + 1] = p.y;
        }
        if (bias) {
#pragma unroll
            for (int j = 0; j < 8; j++) v[j] += bias[tx * 8 + j];
        }
        float4 o0 = { v[0], v[1], v[2], v[3] };
        float4 o1 = { v[4], v[5], v[6], v[7] };
        *reinterpret_cast<float4*>(Cb + (long long)row * 128 + tx * 8) = o0;
        *reinterpret_cast<float4*>(Cb + (long long)row * 128 + tx * 8 + 4) = o1;
        if (doStats) {
#pragma unroll
            for (int j = 0; j < 8; j++) { cs[j] += v[j]; cq[j] += v[j] * v[j]; }
        }
    }
    if (doStats) {
        float* red = &As[0][0];
#pragma unroll
        for (int j = 0; j < 8; j++) red[ty * 128 + tx * 8 + j] = cs[j];
        __syncthreads();
        if (t < 128) {
            float s = 0.f;
#pragma unroll
            for (int g = 0; g < 16; g++) s += red[g * 128 + t];
            atomicAdd(&g_sumA[t], s);
        }
        __syncthreads();
#pragma unroll
        for (int j = 0; j < 8; j++) red[ty * 128 + tx * 8 + j] = cq[j];
        __syncthreads();
        if (t < 128) {
            float s = 0.f;
#pragma unroll
            for (int g = 0; g < 16; g++) s += red[g * 128 + t];
            atomicAdd(&g_ssA[t], s);
        }
    }
}

// ================= warp-per-node aggregation =================
// MODE 0: gcn+bias, 1: gcn+bias+softmax, 2: plain sum
template<int MODE, bool STATS>
__global__ __launch_bounds__(256) void k_aggw(
    const float* __restrict__ in, const float* __restrict__ bias, float* __restrict__ out)
{
    __shared__ float sred[8][128];
    int t = threadIdx.x, w = t >> 5, lane = t & 31;
    int i = blockIdx.x * 8 + w;
    int e0 = g_off[i], n = g_deg[i];
    float ax = 0.f, ay = 0.f, az = 0.f, aw = 0.f;
    for (int c0 = 0; c0 < n; c0 += 32) {
        int m = n - c0; if (m > 32) m = 32;
        int src = 0; float dv = 0.f;
        if (lane < m) {
            src = g_srcbuf[e0 + c0 + lane];
            if (MODE != 2) dv = g_dinv[src];
        }
        for (int kk = 0; kk < m; kk++) {
            int s = __shfl_sync(0xffffffffu, src, kk);
            float4 hv = *reinterpret_cast<const float4*>(in + (long long)s * 128 + lane * 4);
            if (MODE == 2) {
                ax += hv.x; ay += hv.y; az += hv.z; aw += hv.w;
            } else {
                float d = __shfl_sync(0xffffffffu, dv, kk);
                ax += d * hv.x; ay += d * hv.y; az += d * hv.z; aw += d * hv.w;
            }
        }
    }
    float vx, vy, vz, vw;
    if (MODE != 2) {
        float di = g_dinv[i];
        float4 hv = *reinterpret_cast<const float4*>(in + (long long)i * 128 + lane * 4);
        vx = di * (ax + di * hv.x) + bias[lane * 4 + 0];
        vy = di * (ay + di * hv.y) + bias[lane * 4 + 1];
        vz = di * (az + di * hv.z) + bias[lane * 4 + 2];
        vw = di * (aw + di * hv.w) + bias[lane * 4 + 3];
    } else {
        vx = ax; vy = ay; vz = az; vw = aw;
    }
    if (MODE == 1) {
        float mx = fmaxf(fmaxf(vx, vy), fmaxf(vz, vw));
#pragma unroll
        for (int o = 16; o; o >>= 1) mx = fmaxf(mx, __shfl_xor_sync(0xffffffffu, mx, o));
        vx = expf(vx - mx); vy = expf(vy - mx); vz = expf(vz - mx); vw = expf(vw - mx);
        float sm = vx + vy + vz + vw;
#pragma unroll
        for (int o = 16; o; o >>= 1) sm += __shfl_xor_sync(0xffffffffu, sm, o);
        float inv = 1.f / sm;
        vx *= inv; vy *= inv; vz *= inv; vw *= inv;
    }
    float4 o4 = { vx, vy, vz, vw };
    *reinterpret_cast<float4*>(out + (long long)i * 128 + lane * 4) = o4;
    if (STATS) {
        sred[w][lane * 4 + 0] = vx; sred[w][lane * 4 + 1] = vy;
        sred[w][lane * 4 + 2] = vz; sred[w][lane * 4 + 3] = vw;
        __syncthreads();
        if (t < 128) {
            float s = 0.f, q = 0.f;
#pragma unroll
            for (int ww = 0; ww < 8; ww++) { float v = sred[ww][t]; s += v; q += v * v; }
            atomicAdd(&g_sumB[t], s);
            atomicAdd(&g_ssB[t], q);
        }
    }
}

// agg of x (64 ch) -> TRANSPOSED axT [64][NNODES]
__global__ __launch_bounds__(256) void k_aggx(const float* __restrict__ x) {
    __shared__ float stg[64 * 8];
    int t = threadIdx.x, w = t >> 5, lane = t & 31;
    int i = blockIdx.x * 8 + w;
    int e0 = g_off[i], n = g_deg[i];
    float ax = 0.f, ay = 0.f;
    for (int c0 = 0; c0 < n; c0 += 32) {
        int m = n - c0; if (m > 32) m = 32;
        int src = 0; float dv = 0.f;
        if (lane < m) { src = g_srcbuf[e0 + c0 + lane]; dv = g_dinv[src]; }
        for (int kk = 0; kk < m; kk++) {
            int s = __shfl_sync(0xffffffffu, src, kk);
            float d = __shfl_sync(0xffffffffu, dv, kk);
            float2 hv = *reinterpret_cast<const float2*>(x + (long long)s * 64 + lane * 2);
            ax += d * hv.x; ay += d * hv.y;
        }
    }
    float di = g_dinv[i];
    float2 hv = *reinterpret_cast<const float2*>(x + (long long)i * 64 + lane * 2);
    ax = di * (ax + di * hv.x);
    ay = di * (ay + di * hv.y);
    stg[(lane * 2 + 0) * 8 + w] = ax;
    stg[(lane * 2 + 1) * 8 + w] = ay;
    __syncthreads();
    if (t < 128) {
        int c = t >> 1, p = (t & 1) * 4;
        float4 v = *reinterpret_cast<const float4*>(&stg[c * 8 + p]);
        *reinterpret_cast<float4*>(g_axT + (long long)c * NNODES + blockIdx.x * 8 + p) = v;
    }
}

// ================= BN+SiLU(+res) apply, writes h and hT =================
__global__ __launch_bounds__(256) void k_bnapply_t(
    const float* __restrict__ y, const float* __restrict__ res,
    float* __restrict__ h, float* __restrict__ hT,
    const float* __restrict__ gw, const float* __restrict__ be,
    const float* __restrict__ sumArr, const float* __restrict__ ssArr)
{
    __shared__ float tile[32][33];
    __shared__ float sc[32], sh[32];
    int t = threadIdx.x;
    int lx = t & 31, ly = t >> 5;
    int n0 = blockIdx.x * 32, c0 = blockIdx.y * 32;
    if (t < 32) {
        int c = c0 + t;
        float m = sumArr[c] * (1.f / NNODES);
        float var = ssArr[c] * (1.f / NNODES) - m * m;
        float s = gw[c] * rsqrtf(var + 1e-5f);
        sc[t] = s;
        sh[t] = be[c] - s * m;
    }
    __syncthreads();
    for (int i = ly; i < 32; i += 8) {
        long long idx = (long long)(n0 + i) * 128 + c0 + lx;
        float v = y[idx];
        v = sc[lx] * v + sh[lx];
        v = v / (1.f + __expf(-v));
        if (res) v += res[idx];
        h[idx] = v;
        tile[i][lx] = v;
    }
    __syncthreads();
    for (int i = ly; i < 32; i += 8)
        hT[(long long)(c0 + i) * NNODES + n0 + lx] = tile[lx][i];
}

// ================= reduce 8 partials + dinv2 + An; reset stack-2 state =================
__global__ __launch_bounds__(256) void k_reduce_an() {
    int b = blockIdx.x, t = threadIdx.x;
    if (b == 0 && t < 128) {
        g_s2a[t] = 0.f; g_q2a[t] = 0.f; g_s2b[t] = 0.f; g_q2b[t] = 0.f;
        if (t == 0) g_bar = 0;
    }
    const long long PS = (long long)NB * CH * CH;
    const long long BO = (long long)b * CH * CH;
    __shared__ float sd[128];
    for (int idx = t; idx < CH * CH; idx += 256) {
        float s = 0.f;
#pragma unroll
        for (int p = 0; p < 8; p++) s += g_xpart[p * PS + BO + idx];
        g_x2[BO + idx] = s;
    }
    int w = t >> 5, lane = t & 31;
    for (int r = w; r < 128; r += 8) {
        float rsum = 0.f;
#pragma unroll
        for (int q = 0; q < 4; q++) {
            int idx = r * 128 + lane + q * 32;
            float s = 0.f;
#pragma unroll
            for (int p = 0; p < 8; p++) s += g_apart[p * PS + BO + idx];
            g_A2[BO + idx] = s;
            rsum += s;
        }
#pragma unroll
        for (int o = 16; o; o >>= 1) rsum += __shfl_down_sync(0xffffffffu, rsum, o);
        if (lane == 0) sd[r] = rsqrtf(rsum + 1.0f);
    }
    __syncthreads();
    for (int idx = t; idx < CH * CH; idx += 256) {
        int i = idx >> 7, j = idx & 127;
        float v = g_A2[BO + idx] + (i == j ? 1.f : 0.f);
        g_An[BO + idx] = sd[i] * v * sd[j];
    }
}

// ================= fused stack-2 (32 blocks, grid barrier) =================
__device__ __forceinline__ void gridbar(int target) {
    __syncthreads();
    __threadfence();
    if (threadIdx.x == 0) {
        atomicAdd(&g_bar, 1);
        while (*(volatile int*)&g_bar < target) __nanosleep(64);
    }
    __syncthreads();
    __threadfence();
}

__device__ __forceinline__ void gemm_sm128(const float* __restrict__ P, const float* __restrict__ Q,
                                           unsigned long long acc2[8][4], int tx, int ty)
{
#pragma unroll
    for (int i = 0; i < 8; i++)
#pragma unroll
        for (int j = 0; j < 4; j++) acc2[i][j] = 0ull;
#pragma unroll 2
    for (int k = 0; k < 128; k++) {
        float a[8];
#pragma unroll
        for (int i = 0; i < 8; i++) a[i] = P[(ty * 8 + i) * 128 + k];
        const unsigned long long* Qp =
            reinterpret_cast<const unsigned long long*>(&Q[k * 128 + tx * 8]);
        unsigned long long b0 = Qp[0], b1 = Qp[1], b2 = Qp[2], b3 = Qp[3];
#pragma unroll
        for (int i = 0; i < 8; i++) {
            unsigned long long ad = dup_f32(a[i]);
            ffma2(acc2[i][0], ad, b0);
            ffma2(acc2[i][1], ad, b1);
            ffma2(acc2[i][2], ad, b2);
            ffma2(acc2[i][3], ad, b3);
        }
    }
}

__global__ __launch_bounds__(256) void k_stack2(
    const float* __restrict__ w2a, const float* __restrict__ b2a,
    const float* __restrict__ g2a, const float* __restrict__ be2a,
    const float* __restrict__ w2b, const float* __restrict__ b2b,
    const float* __restrict__ g2b, const float* __restrict__ be2b,
    const float* __restrict__ wl, const float* __restrict__ bl,
    float* __restrict__ out, int out_size)
{
    extern __shared__ __align__(16) float sm2[];
    float* AN = sm2;
    float* XB = sm2 + 16384;
    float* WB = sm2 + 32768;
    __shared__ float red[2048];
    __shared__ float gv[128];
    __shared__ float lg[10];
    __shared__ float lse;
    int b = blockIdx.x, t = threadIdx.x, tx = t & 15, ty = t >> 4;
    const float INVN = 1.f / (NB * CH);

    {
        const float4* pAn = (const float4*)(g_An + (long long)b * 16384);
        const float4* pX2 = (const float4*)(g_x2 + (long long)b * 16384);
        const float4* pWa = (const float4*)w2a;
        float4* An4 = (float4*)AN; float4* X4 = (float4*)XB; float4* W4 = (float4*)WB;
        for (int i = t; i < 4096; i += 256) { An4[i] = pAn[i]; X4[i] = pX2[i]; W4[i] = pWa[i]; }
    }
    __syncthreads();

    unsigned long long acc2[8][4];
    float cs[8], cq[8];

    // tmp = x2 @ w2a -> XB
    gemm_sm128(XB, WB, acc2, tx, ty);
    __syncthreads();
#pragma unroll
    for (int i = 0; i < 8; i++)
#pragma unroll
        for (int j = 0; j < 4; j++) {
            float2 p = u2f(acc2[i][j]);
            XB[(ty * 8 + i) * 128 + tx * 8 + 2 * j] = p.x;
            XB[(ty * 8 + i) * 128 + tx * 8 + 2 * j + 1] = p.y;
        }
    __syncthreads();

    // y = An @ tmp + b2a -> WB, stats
    gemm_sm128(AN, XB, acc2, tx, ty);
    __syncthreads();
#pragma unroll
    for (int j = 0; j < 8; j++) { cs[j] = 0.f; cq[j] = 0.f; }
#pragma unroll
    for (int i = 0; i < 8; i++)
#pragma unroll
        for (int j = 0; j < 4; j++) {
            float2 p = u2f(acc2[i][j]);
            float v0 = p.x + b2a[tx * 8 + 2 * j];
            float v1 = p.y + b2a[tx * 8 + 2 * j + 1];
            WB[(ty * 8 + i) * 128 + tx * 8 + 2 * j] = v0;
            WB[(ty * 8 + i) * 128 + tx * 8 + 2 * j + 1] = v1;
            cs[2 * j] += v0; cq[2 * j] += v0 * v0;
            cs[2 * j + 1] += v1; cq[2 * j + 1] += v1 * v1;
        }
#pragma unroll
    for (int j = 0; j < 8; j++) red[ty * 128 + tx * 8 + j] = cs[j];
    __syncthreads();
    if (t < 128) { float s = 0.f; for (int g = 0; g < 16; g++) s += red[g * 128 + t]; atomicAdd(&g_s2a[t], s); }
    __syncthreads();
#pragma unroll
    for (int j = 0; j < 8; j++) red[ty * 128 + tx * 8 + j] = cq[j];
    __syncthreads();
    if (t < 128) { float s = 0.f; for (int g = 0; g < 16; g++) s += red[g * 128 + t]; atomicAdd(&g_q2a[t], s); }

    gridbar(NB);

    // h2 = silu(bn(WB)) -> XB
    float scv[8], shv[8];
#pragma unroll
    for (int j = 0; j < 8; j++) {
        int c = tx * 8 + j;
        float m = g_s2a[c] * INVN;
        float var = g_q2a[c] * INVN - m * m;
        float s = g2a[c] * rsqrtf(var + 1e-5f);
        scv[j] = s; shv[j] = be2a[c] - s * m;
    }
#pragma unroll
    for (int i = 0; i < 8; i++)
#pragma unroll
        for (int j = 0; j < 8; j++) {
            float v = WB[(ty * 8 + i) * 128 + tx * 8 + j];
            v = scv[j] * v + shv[j];
            v = v / (1.f + __expf(-v));
            XB[(ty * 8 + i) * 128 + tx * 8 + j] = v;
        }
    __syncthreads();

    // WB := w2b
    {
        const float4* pWb = (const float4*)w2b;
        float4* W4 = (float4*)WB;
        for (int i = t; i < 4096; i += 256) W4[i] = pWb[i];
    }
    __syncthreads();

    // tmp2 = h2 @ w2b -> WB
    gemm_sm128(XB, WB, acc2, tx, ty);
    __syncthreads();
#pragma unroll
    for (int i = 0; i < 8; i++)
#pragma unroll
        for (int j = 0; j < 4; j++) {
            float2 p = u2f(acc2[i][j]);
            WB[(ty * 8 + i) * 128 + tx * 8 + 2 * j] = p.x;
            WB[(ty * 8 + i) * 128 + tx * 8 + 2 * j + 1] = p.y;
        }
    __syncthreads();

    // y2 = An @ tmp2 (acc2 stays live), stats with +b2b
    gemm_sm128(AN, WB, acc2, tx, ty);
#pragma unroll
    for (int j = 0; j < 8; j++) { cs[j] = 0.f; cq[j] = 0.f; }
#pragma unroll
    for (int i = 0; i < 8; i++)
#pragma unroll
        for (int j = 0; j < 4; j++) {
            float2 p = u2f(acc2[i][j]);
            float v0 = p.x + b2b[tx * 8 + 2 * j];
            float v1 = p.y + b2b[tx * 8 + 2 * j + 1];
            cs[2 * j] += v0; cq[2 * j] += v0 * v0;
            cs[2 * j + 1] += v1; cq[2 * j + 1] += v1 * v1;
        }
    __syncthreads();
#pragma unroll
    for (int j = 0; j < 8; j++) red[ty * 128 + tx * 8 + j] = cs[j];
    __syncthreads();
    if (t < 128) { float s = 0.f; for (int g = 0; g < 16; g++) s += red[g * 128 + t]; atomicAdd(&g_s2b[t], s); }
    __syncthreads();
#pragma unroll
    for (int j = 0; j < 8; j++) red[ty * 128 + tx * 8 + j] = cq[j];
    __syncthreads();
    if (t < 128) { float s = 0.f; for (int g = 0; g < 16; g++) s += red[g * 128 + t]; atomicAdd(&g_q2b[t], s); }

    gridbar(2 * NB);

    // h2fin = XB + silu(bn(y2)); column sums -> head
#pragma unroll
    for (int j = 0; j < 8; j++) {
        int c = tx * 8 + j;
        float m = g_s2b[c] * INVN;
        float var = g_q2b[c] * INVN - m * m;
        float s = g2b[c] * rsqrtf(var + 1e-5f);
        scv[j] = s; shv[j] = be2b[c] - s * m;
    }
    float colsum[8];
#pragma unroll
    for (int j = 0; j < 8; j++) colsum[j] = 0.f;
#pragma unroll
    for (int i = 0; i < 8; i++)
#pragma unroll
        for (int j = 0; j < 4; j++) {
            float2 p = u2f(acc2[i][j]);
            float v0 = scv[2 * j] * (p.x + b2b[tx * 8 + 2 * j]) + shv[2 * j];
            float v1 = scv[2 * j + 1] * (p.y + b2b[tx * 8 + 2 * j + 1]) + shv[2 * j + 1];
            v0 = v0 / (1.f + __expf(-v0));
            v1 = v1 / (1.f + __expf(-v1));
            v0 += XB[(ty * 8 + i) * 128 + tx * 8 + 2 * j];
            v1 += XB[(ty * 8 + i) * 128 + tx * 8 + 2 * j + 1];
            colsum[2 * j] += v0;
            colsum[2 * j + 1] += v1;
        }
    __syncthreads();
#pragma unroll
    for (int j = 0; j < 8; j++) red[ty * 128 + tx * 8 + j] = colsum[j];
    __syncthreads();
    if (t < 128) {
        float s = 0.f;
        for (int g = 0; g < 16; g++) s += red[g * 128 + t];
        gv[t] = s * (1.f / 32.f);
    }
    __syncthreads();
    if (t < 10) {
        float a = bl[t];
        for (int k = 0; k < 128; k++) a += gv[k] * wl[k * 10 + t];
        lg[t] = a;
    }
    __syncthreads();
    if (t == 0) {
        float mx = -1e30f;
        for (int j = 0; j < 10; j++) mx = fmaxf(mx, lg[j]);
        float se = 0.f;
        for (int j = 0; j < 10; j++) se += expf(lg[j] - mx);
        lse = mx + logf(se);
    }
    __syncthreads();
    if (t < 10) {
        int o = b * 10 + t;
        if (o < out_size) out[o] = lg[t] - lse;
    }
    if (b == 0) {
        for (int idx = NB * 10 + t; idx < out_size; idx += 256) out[idx] = 0.f;
    }
}

// ================= host orchestration =================
extern "C" void kernel_launch(void* const* d_in, const int* in_sizes, int n_in,
                              void* d_out, int out_size) {
    const float* x    = (const float*)d_in[0];
    const int*   ei   = (const int*)  d_in[1];
    const float* w1a  = (const float*)d_in[4];
    const float* b1a  = (const float*)d_in[5];
    const float* g1a  = (const float*)d_in[6];
    const float* be1a = (const float*)d_in[7];
    const float* w1b  = (const float*)d_in[8];
    const float* b1b  = (const float*)d_in[9];
    const float* g1b  = (const float*)d_in[10];
    const float* be1b = (const float*)d_in[11];
    const float* wp1  = (const float*)d_in[12];
    const float* bp1  = (const float*)d_in[13];
    const float* w2a  = (const float*)d_in[14];
    const float* b2a  = (const float*)d_in[15];
    const float* g2a  = (const float*)d_in[16];
    const float* be2a = (const float*)d_in[17];
    const float* w2b  = (const float*)d_in[18];
    const float* b2b  = (const float*)d_in[19];
    const float* g2b  = (const float*)d_in[20];
    const float* be2b = (const float*)d_in[21];
    // d_in[22]=wp2, d_in[23]=bp2 dead (softmax rows sum to 1)
    const float* wl   = (const float*)d_in[24];
    const float* bl   = (const float*)d_in[25];
    float* outp = (float*)d_out;
    (void)n_in; (void)in_sizes;

    float *p_lin, *p_y, *p_h, *p_s, *p_t, *p_axT, *p_hT, *p_xpart, *p_apart;
    float *p_sumA, *p_ssA, *p_sumB, *p_ssB;
    cudaGetSymbolAddress((void**)&p_lin,   g_lin);
    cudaGetSymbolAddress((void**)&p_y,     g_y);
    cudaGetSymbolAddress((void**)&p_h,     g_h);
    cudaGetSymbolAddress((void**)&p_s,     g_s);
    cudaGetSymbolAddress((void**)&p_t,     g_t);
    cudaGetSymbolAddress((void**)&p_axT,   g_axT);
    cudaGetSymbolAddress((void**)&p_hT,    g_hT);
    cudaGetSymbolAddress((void**)&p_xpart, g_xpart);
    cudaGetSymbolAddress((void**)&p_apart, g_apart);
    cudaGetSymbolAddress((void**)&p_sumA,  g_sumA);
    cudaGetSymbolAddress((void**)&p_ssA,   g_ssA);
    cudaGetSymbolAddress((void**)&p_sumB,  g_sumB);
    cudaGetSymbolAddress((void**)&p_ssB,   g_ssB);

    static bool attrDone = false;
    if (!attrDone) {
        cudaFuncSetAttribute(k_stack2, cudaFuncAttributeMaxDynamicSharedMemorySize, 196608);
        attrDone = true;
    }

    // graph structure
    k_zero_deg<<<NNODES / 256, 256>>>();
    k_deg  <<<NEDGES / 256, 256>>>(ei);
    k_alloc<<<NNODES / 1024, 1024>>>();
    k_fill <<<NEDGES / 256, 256>>>(ei);

    // stack 1, layer a
    k_aggx<<<NNODES / 8, 256>>>(x);
    k_gemmu<false><<<256, 256>>>(p_axT, w1a, nullptr, b1a, p_y, nullptr, NNODES, 64, 1);
    k_bnapply_t<<<dim3(NNODES / 32, 4), 256>>>(p_y, nullptr, p_h, p_hT, g1a, be1a, p_sumA, p_ssA);

    // stack 1, layer b (residual)
    k_gemmu<false><<<256, 256>>>(p_hT, w1b, nullptr, nullptr, p_lin, nullptr, NNODES, 128, 0);
    k_aggw<0, true><<<NNODES / 8, 256>>>(p_lin, b1b, p_y);
    k_bnapply_t<<<dim3(NNODES / 32, 4), 256>>>(p_y, p_h, p_h, p_hT, g1b, be1b, p_sumB, p_ssB);

    // pooling 1
    k_gemmu<false><<<256, 256>>>(p_hT, wp1, nullptr, nullptr, p_lin, nullptr, NNODES, 128, 0);
    k_aggw<1, false><<<NNODES / 8, 256>>>(p_lin, bp1, p_s);
    k_aggw<2, false><<<NNODES / 8, 256>>>(p_s, nullptr, p_t);

    // pooled einsums (x2 and A2 partials in one launch), reduce + An
    k_gemmu<true><<<dim3(1, 16, NB), 256>>>(p_s, p_h, p_t, nullptr, p_xpart, p_apart, 128, 128, 0);
    k_reduce_an<<<NB, 256>>>();

    // fused stack 2 + head
    k_stack2<<<NB, 256, 196608>>>(w2a, b2a, g2a, be2a, w2b, b2b, g2b, be2b, wl, bl, outp, out_size);
}

// round 7
// speedup vs baseline: 1.5409x; 1.0562x over previous
#include <cuda_runtime.h>
#include <cuda_bf16.h>
#include <math.h>
#include <stdint.h>

#define NNODES 32768
#define NEDGES 524288
#define NB     32
#define NPG    1024
#define CH     128
#define CIN    64

// ================= helpers =================
__device__ __forceinline__ uint32_t smem_u32(const void* p) {
    uint32_t a;
    asm("{ .reg .u64 t; cvta.to.shared.u64 t, %1; cvt.u32.u64 %0, t; }" : "=r"(a) : "l"(p));
    return a;
}
__device__ __forceinline__ void ffma2(unsigned long long& d, unsigned long long a, unsigned long long b) {
    asm("fma.rn.f32x2 %0, %1, %2, %0;" : "+l"(d) : "l"(a), "l"(b));
}
__device__ __forceinline__ unsigned long long dup_f32(float v) {
    unsigned long long r;
    asm("mov.b64 %0, {%1, %1};" : "=l"(r) : "f"(v));
    return r;
}
__device__ __forceinline__ float2 u2f(unsigned long long v) {
    float2 f;
    asm("mov.b64 {%0, %1}, %2;" : "=f"(f.x), "=f"(f.y) : "l"(v));
    return f;
}
#define CP_ASYNC16(dst, src) asm volatile("cp.async.ca.shared.global [%0], [%1], 16;" :: "r"(dst), "l"(src))
#define CP_COMMIT()          asm volatile("cp.async.commit_group;" ::: "memory")
#define CP_WAIT(n)           asm volatile("cp.async.wait_group %0;" :: "n"(n) : "memory")

#define MMA_BF16(cf, a0, a1, a2, a3, b0, b1) \
    asm volatile("mma.sync.aligned.m16n8k16.row.col.f32.bf16.bf16.f32 " \
        "{%0,%1,%2,%3},{%4,%5,%6,%7},{%8,%9},{%0,%1,%2,%3};" \
        : "+f"((cf)[0]), "+f"((cf)[1]), "+f"((cf)[2]), "+f"((cf)[3]) \
        : "r"(a0), "r"(a1), "r"(a2), "r"(a3), "r"(b0), "r"(b1))

__device__ __forceinline__ uint32_t pack_hi(float a, float b) {
    __nv_bfloat162 h;
    h.x = __float2bfloat16_rn(a); h.y = __float2bfloat16_rn(b);
    return *reinterpret_cast<uint32_t*>(&h);
}
__device__ __forceinline__ uint32_t pack_lo(float a, float b) {
    __nv_bfloat16 ha = __float2bfloat16_rn(a), hb = __float2bfloat16_rn(b);
    __nv_bfloat162 l;
    l.x = __float2bfloat16_rn(a - __bfloat162float(ha));
    l.y = __float2bfloat16_rn(b - __bfloat162float(hb));
    return *reinterpret_cast<uint32_t*>(&l);
}

// ================= device scratch =================
__device__ int   g_deg[NNODES];
__device__ int   g_off[NNODES];
__device__ int   g_cur[NNODES];
__device__ int   g_total;
__device__ int   g_srcbuf[NEDGES];
__device__ float g_dinv[NNODES];

__device__ float g_lin[NNODES * CH];
__device__ float g_y  [NNODES * CH];
__device__ float g_h  [NNODES * CH];      // h_a (residual)
__device__ float g_s  [NNODES * CH];

__device__ __align__(16) __nv_bfloat16 g_axh[NNODES * CIN], g_axl[NNODES * CIN];
__device__ __align__(16) __nv_bfloat16 g_hah[NNODES * CH],  g_hal[NNODES * CH];
__device__ __align__(16) __nv_bfloat16 g_hbh[NNODES * CH],  g_hbl[NNODES * CH];
__device__ __align__(16) __nv_bfloat16 g_hTh[CH * NNODES],  g_hTl[CH * NNODES];
__device__ __align__(16) __nv_bfloat16 g_sTh[CH * NNODES],  g_sTl[CH * NNODES];
__device__ __align__(16) __nv_bfloat16 g_tTh[CH * NNODES],  g_tTl[CH * NNODES];
__device__ __align__(16) __nv_bfloat16 g_w1ah[CH * CIN], g_w1al[CH * CIN];
__device__ __align__(16) __nv_bfloat16 g_w1bh[CH * CH],  g_w1bl[CH * CH];
__device__ __align__(16) __nv_bfloat16 g_wp1h[CH * CH],  g_wp1l[CH * CH];

__device__ float g_xpart[8 * NB * CH * CH];
__device__ float g_apart[8 * NB * CH * CH];
__device__ float g_x2  [NB * CH * CH];
__device__ float g_A2  [NB * CH * CH];
__device__ float g_An  [NB * CH * CH];

__device__ float g_sumA[CH], g_ssA[CH], g_sumB[CH], g_ssB[CH];
__device__ float g_s2a[CH], g_q2a[CH], g_s2b[CH], g_q2b[CH];
__device__ int   g_bar;

// ================= graph structure =================
__global__ void k_zero_deg() {
    int i = blockIdx.x * 256 + threadIdx.x;
    if (i < NNODES) g_deg[i] = 0;
    if (i < 128) { g_sumA[i] = 0.f; g_ssA[i] = 0.f; g_sumB[i] = 0.f; g_ssB[i] = 0.f; }
    if (i == 0) g_total = 0;
}
__global__ void k_deg(const int* __restrict__ ei) {
    int e = blockIdx.x * 256 + threadIdx.x;
    if (e < NEDGES) atomicAdd(&g_deg[ei[NEDGES + e]], 1);
}
__global__ void k_alloc() {
    int t = threadIdx.x;
    int node = blockIdx.x * 1024 + t;
    int lane = t & 31;
    int deg = g_deg[node];
    int incl = deg;
#pragma unroll
    for (int d = 1; d < 32; d <<= 1) {
        int v = __shfl_up_sync(0xffffffffu, incl, d);
        if (lane >= d) incl += v;
    }
    int tot = __shfl_sync(0xffffffffu, incl, 31);
    int base = 0;
    if (lane == 31) base = atomicAdd(&g_total, tot);
    base = __shfl_sync(0xffffffffu, base, 31);
    int off = base + incl - deg;
    g_off[node] = off;
    g_cur[node] = off;
    g_dinv[node] = rsqrtf((float)deg + 1.0f);
}
__global__ void k_fill(const int* __restrict__ ei) {
    int e = blockIdx.x * 256 + threadIdx.x;
    if (e < NEDGES) {
        int d = ei[NEDGES + e];
        int p = atomicAdd(&g_cur[d], 1);
        g_srcbuf[p] = ei[e];
    }
}

// ================= weights: transpose + bf16 split =================
__global__ void k_wsplit(const float* __restrict__ w1a, const float* __restrict__ w1b,
                         const float* __restrict__ wp1) {
    int idx = blockIdx.x * 256 + threadIdx.x;      // 160 blocks = 40960
    if (idx < 8192) {                              // w1aT [128 n][64 k]
        int n = idx >> 6, k = idx & 63;
        float v = w1a[k * 128 + n];
        __nv_bfloat16 h = __float2bfloat16_rn(v);
        g_w1ah[idx] = h;
        g_w1al[idx] = __float2bfloat16_rn(v - __bfloat162float(h));
    } else if (idx < 24576) {                      // w1bT [128][128]
        int j = idx - 8192;
        int n = j >> 7, k = j & 127;
        float v = w1b[k * 128 + n];
        __nv_bfloat16 h = __float2bfloat16_rn(v);
        g_w1bh[j] = h;
        g_w1bl[j] = __float2bfloat16_rn(v - __bfloat162float(h));
    } else if (idx < 40960) {                      // wp1T [128][128]
        int j = idx - 24576;
        int n = j >> 7, k = j & 127;
        float v = wp1[k * 128 + n];
        __nv_bfloat16 h = __float2bfloat16_rn(v);
        g_wp1h[j] = h;
        g_wp1l[j] = __float2bfloat16_rn(v - __bfloat162float(h));
    }
}

// ================= bf16-split mma.sync GEMM =================
// C[m][n] = sum_k A[m][k]*B[n][k]; A,B bf16 hi/lo, fp32 accum via 3 products.
// 128x128 tile, 8 warps (4m x 2n), K-step 16, cp.async double buffer.
template<bool POOLED, bool STATS>
__global__ __launch_bounds__(256) void k_mma(
    const __nv_bfloat16* __restrict__ Ah, const __nv_bfloat16* __restrict__ Al, long long pA,
    const __nv_bfloat16* __restrict__ B1h, const __nv_bfloat16* __restrict__ B1l,
    const __nv_bfloat16* __restrict__ B2h, const __nv_bfloat16* __restrict__ B2l, long long pB,
    const float* __restrict__ bias, float* __restrict__ C1, float* __restrict__ C2, int K)
{
    extern __shared__ __align__(16) char smem[];
    __nv_bfloat16* SB = reinterpret_cast<__nv_bfloat16*>(smem);   // [2][4][3072]
    float* sstat = reinterpret_cast<float*>(smem + 49152);        // 256 floats
    int t = threadIdx.x, lane = t & 31;
    int warpm = ((t >> 5) & 3) * 32, warpn = (t >> 7) * 64;

    const __nv_bfloat16 *Ahb, *Alb, *Bhb, *Blb;
    float* Cb;
    if (POOLED) {
        int g = blockIdx.z;
        int half = blockIdx.y >> 3, chunk = blockIdx.y & 7;
        long long ko = (long long)g * 1024 + (long long)chunk * 128;
        Ahb = Ah + ko; Alb = Al + ko;
        Bhb = (half ? B2h : B1h) + ko;
        Blb = (half ? B2l : B1l) + ko;
        Cb = (half ? C2 : C1) + (long long)(chunk * NB + g) * (CH * CH);
    } else {
        long long m0 = (long long)blockIdx.x * 128;
        Ahb = Ah + m0 * pA; Alb = Al + m0 * pA;
        Bhb = B1h; Blb = B1l;
        Cb = C1 + m0 * 128;
    }
    if (STATS) { sstat[t] = 0.f; }

    uint32_t sbase = smem_u32(SB);
    int sr = t >> 1, sc = t & 1;
    uint32_t dofs = sbase + sr * 48 + sc * 16;
    // stage 0
    CP_ASYNC16(dofs,         Ahb + (long long)sr * pA + sc * 8);
    CP_ASYNC16(dofs + 6144,  Alb + (long long)sr * pA + sc * 8);
    CP_ASYNC16(dofs + 12288, Bhb + (long long)sr * pB + sc * 8);
    CP_ASYNC16(dofs + 18432, Blb + (long long)sr * pB + sc * 8);
    CP_COMMIT();

    float c[2][8][4];
#pragma unroll
    for (int i = 0; i < 2; i++)
#pragma unroll
        for (int j = 0; j < 8; j++)
#pragma unroll
            for (int q = 0; q < 4; q++) c[i][j][q] = 0.f;

    int g8 = lane >> 2, kc = (lane & 3) * 2;
    int NT = K >> 4;
    for (int kt = 0; kt < NT; kt++) {
        if (kt + 1 < NT) {
            int k0 = (kt + 1) << 4;
            uint32_t d2 = dofs + ((kt + 1) & 1) * 24576;
            CP_ASYNC16(d2,         Ahb + (long long)sr * pA + k0 + sc * 8);
            CP_ASYNC16(d2 + 6144,  Alb + (long long)sr * pA + k0 + sc * 8);
            CP_ASYNC16(d2 + 12288, Bhb + (long long)sr * pB + k0 + sc * 8);
            CP_ASYNC16(d2 + 18432, Blb + (long long)sr * pB + k0 + sc * 8);
            CP_COMMIT();
            CP_WAIT(1);
        } else {
            CP_WAIT(0);
        }
        __syncthreads();
        const __nv_bfloat16* P = SB + (kt & 1) * 12288;
        uint32_t ah[2][4], al[2][4];
#pragma unroll
        for (int mt = 0; mt < 2; mt++) {
            int mb = warpm + mt * 16 + g8;
            ah[mt][0] = *(const uint32_t*)(P + mb * 24 + kc);
            ah[mt][1] = *(const uint32_t*)(P + (mb + 8) * 24 + kc);
            ah[mt][2] = *(const uint32_t*)(P + mb * 24 + kc + 8);
            ah[mt][3] = *(const uint32_t*)(P + (mb + 8) * 24 + kc + 8);
            al[mt][0] = *(const uint32_t*)(P + 3072 + mb * 24 + kc);
            al[mt][1] = *(const uint32_t*)(P + 3072 + (mb + 8) * 24 + kc);
            al[mt][2] = *(const uint32_t*)(P + 3072 + mb * 24 + kc + 8);
            al[mt][3] = *(const uint32_t*)(P + 3072 + (mb + 8) * 24 + kc + 8);
        }
#pragma unroll
        for (int nt = 0; nt < 8; nt++) {
            int nb = warpn + nt * 8 + g8;
            uint32_t bh0 = *(const uint32_t*)(P + 6144 + nb * 24 + kc);
            uint32_t bh1 = *(const uint32_t*)(P + 6144 + nb * 24 + kc + 8);
            uint32_t bl0 = *(const uint32_t*)(P + 9216 + nb * 24 + kc);
            uint32_t bl1 = *(const uint32_t*)(P + 9216 + nb * 24 + kc + 8);
#pragma unroll
            for (int mt = 0; mt < 2; mt++) {
                MMA_BF16(c[mt][nt], ah[mt][0], ah[mt][1], ah[mt][2], ah[mt][3], bh0, bh1);
                MMA_BF16(c[mt][nt], ah[mt][0], ah[mt][1], ah[mt][2], ah[mt][3], bl0, bl1);
                MMA_BF16(c[mt][nt], al[mt][0], al[mt][1], al[mt][2], al[mt][3], bh0, bh1);
            }
        }
        __syncthreads();
    }

    // epilogue
    float cs[8][2], cq[8][2];
    if (STATS) {
#pragma unroll
        for (int j = 0; j < 8; j++) { cs[j][0] = cs[j][1] = 0.f; cq[j][0] = cq[j][1] = 0.f; }
    }
#pragma unroll
    for (int mt = 0; mt < 2; mt++) {
        int row = warpm + mt * 16 + g8;
#pragma unroll
        for (int nt = 0; nt < 8; nt++) {
            int col = warpn + nt * 8 + kc;
            float b0 = bias ? bias[col] : 0.f;
            float b1 = bias ? bias[col + 1] : 0.f;
            float v00 = c[mt][nt][0] + b0, v01 = c[mt][nt][1] + b1;
            float v10 = c[mt][nt][2] + b0, v11 = c[mt][nt][3] + b1;
            *reinterpret_cast<float2*>(Cb + (long long)row * 128 + col) = make_float2(v00, v01);
            *reinterpret_cast<float2*>(Cb + (long long)(row + 8) * 128 + col) = make_float2(v10, v11);
            if (STATS) {
                cs[nt][0] += v00 + v10; cq[nt][0] += v00 * v00 + v10 * v10;
                cs[nt][1] += v01 + v11; cq[nt][1] += v01 * v01 + v11 * v11;
            }
        }
    }
    if (STATS) {
        __syncthreads();
#pragma unroll
        for (int nt = 0; nt < 8; nt++) {
            int col = warpn + nt * 8 + kc;
            atomicAdd(&sstat[col], cs[nt][0]);
            atomicAdd(&sstat[col + 1], cs[nt][1]);
            atomicAdd(&sstat[128 + col], cq[nt][0]);
            atomicAdd(&sstat[128 + col + 1], cq[nt][1]);
        }
        __syncthreads();
        if (t < 128) {
            atomicAdd(&g_sumA[t], sstat[t]);
            atomicAdd(&g_ssA[t], sstat[128 + t]);
        }
    }
}

// ================= warp-per-node aggregation =================
// MODE 0: gcn+bias (+stats, fp32 out); 1: gcn+bias+softmax (fp32 out + sT bf16);
// MODE 2: plain sum (tT bf16 only)
template<int MODE>
__global__ __launch_bounds__(256) void k_aggw(
    const float* __restrict__ in, const float* __restrict__ bias, float* __restrict__ out,
    __nv_bfloat16* __restrict__ oTh, __nv_bfloat16* __restrict__ oTl)
{
    __shared__ float sred[8][128];
    __shared__ float st[8][132];
    int t = threadIdx.x, w = t >> 5, lane = t & 31;
    int i = blockIdx.x * 8 + w;
    int e0 = g_off[i], n = g_deg[i];
    float ax = 0.f, ay = 0.f, az = 0.f, aw = 0.f;
    for (int c0 = 0; c0 < n; c0 += 32) {
        int m = n - c0; if (m > 32) m = 32;
        int src = 0; float dv = 0.f;
        if (lane < m) {
            src = g_srcbuf[e0 + c0 + lane];
            if (MODE != 2) dv = g_dinv[src];
        }
        for (int kk = 0; kk < m; kk++) {
            int s = __shfl_sync(0xffffffffu, src, kk);
            float4 hv = *reinterpret_cast<const float4*>(in + (long long)s * 128 + lane * 4);
            if (MODE == 2) {
                ax += hv.x; ay += hv.y; az += hv.z; aw += hv.w;
            } else {
                float d = __shfl_sync(0xffffffffu, dv, kk);
                ax += d * hv.x; ay += d * hv.y; az += d * hv.z; aw += d * hv.w;
            }
        }
    }
    float vx, vy, vz, vw;
    if (MODE != 2) {
        float di = g_dinv[i];
        float4 hv = *reinterpret_cast<const float4*>(in + (long long)i * 128 + lane * 4);
        vx = di * (ax + di * hv.x) + bias[lane * 4 + 0];
        vy = di * (ay + di * hv.y) + bias[lane * 4 + 1];
        vz = di * (az + di * hv.z) + bias[lane * 4 + 2];
        vw = di * (aw + di * hv.w) + bias[lane * 4 + 3];
    } else {
        vx = ax; vy = ay; vz = az; vw = aw;
    }
    if (MODE == 1) {
        float mx = fmaxf(fmaxf(vx, vy), fmaxf(vz, vw));
#pragma unroll
        for (int o = 16; o; o >>= 1) mx = fmaxf(mx, __shfl_xor_sync(0xffffffffu, mx, o));
        vx = expf(vx - mx); vy = expf(vy - mx); vz = expf(vz - mx); vw = expf(vw - mx);
        float sm = vx + vy + vz + vw;
#pragma unroll
        for (int o = 16; o; o >>= 1) sm += __shfl_xor_sync(0xffffffffu, sm, o);
        float inv = 1.f / sm;
        vx *= inv; vy *= inv; vz *= inv; vw *= inv;
    }
    if (MODE != 2) {
        float4 o4 = { vx, vy, vz, vw };
        *reinterpret_cast<float4*>(out + (long long)i * 128 + lane * 4) = o4;
    }
    if (MODE == 0) {
        sred[w][lane * 4 + 0] = vx; sred[w][lane * 4 + 1] = vy;
        sred[w][lane * 4 + 2] = vz; sred[w][lane * 4 + 3] = vw;
        __syncthreads();
        if (t < 128) {
            float s = 0.f, q = 0.f;
#pragma unroll
            for (int ww = 0; ww < 8; ww++) { float v = sred[ww][t]; s += v; q += v * v; }
            atomicAdd(&g_sumB[t], s);
            atomicAdd(&g_ssB[t], q);
        }
    } else {
        // transposed bf16 hi/lo output [128 ch][NNODES]
        st[w][lane * 4 + 0] = vx; st[w][lane * 4 + 1] = vy;
        st[w][lane * 4 + 2] = vz; st[w][lane * 4 + 3] = vw;
        __syncthreads();
        if (t < 128) {
            int c = t;
            float v0 = st[0][c], v1 = st[1][c], v2 = st[2][c], v3 = st[3][c];
            float v4 = st[4][c], v5 = st[5][c], v6 = st[6][c], v7 = st[7][c];
            long long o = (long long)c * NNODES + blockIdx.x * 8;
            uint4 hv, lv;
            hv.x = pack_hi(v0, v1); hv.y = pack_hi(v2, v3);
            hv.z = pack_hi(v4, v5); hv.w = pack_hi(v6, v7);
            lv.x = pack_lo(v0, v1); lv.y = pack_lo(v2, v3);
            lv.z = pack_lo(v4, v5); lv.w = pack_lo(v6, v7);
            *reinterpret_cast<uint4*>(oTh + o) = hv;
            *reinterpret_cast<uint4*>(oTl + o) = lv;
        }
    }
}

// agg of x (64 ch) -> row-major bf16 hi/lo [node][64]
__global__ __launch_bounds__(256) void k_aggx(const float* __restrict__ x) {
    int t = threadIdx.x, w = t >> 5, lane = t & 31;
    int i = blockIdx.x * 8 + w;
    int e0 = g_off[i], n = g_deg[i];
    float ax = 0.f, ay = 0.f;
    for (int c0 = 0; c0 < n; c0 += 32) {
        int m = n - c0; if (m > 32) m = 32;
        int src = 0; float dv = 0.f;
        if (lane < m) { src = g_srcbuf[e0 + c0 + lane]; dv = g_dinv[src]; }
        for (int kk = 0; kk < m; kk++) {
            int s = __shfl_sync(0xffffffffu, src, kk);
            float d = __shfl_sync(0xffffffffu, dv, kk);
            float2 hv = *reinterpret_cast<const float2*>(x + (long long)s * 64 + lane * 2);
            ax += d * hv.x; ay += d * hv.y;
        }
    }
    float di = g_dinv[i];
    float2 hv = *reinterpret_cast<const float2*>(x + (long long)i * 64 + lane * 2);
    ax = di * (ax + di * hv.x);
    ay = di * (ay + di * hv.y);
    long long o = (long long)i * 64 + lane * 2;
    *reinterpret_cast<uint32_t*>(g_axh + o) = pack_hi(ax, ay);
    *reinterpret_cast<uint32_t*>(g_axl + o) = pack_lo(ax, ay);
}

// ================= BN+SiLU(+res); emits fp32 h (opt), row bf16, trans bf16 (opt) =================
template<bool RES, bool WH, bool WT>
__global__ __launch_bounds__(256) void k_bn(
    const float* __restrict__ y, const float* __restrict__ res, float* __restrict__ h,
    __nv_bfloat16* __restrict__ rh, __nv_bfloat16* __restrict__ rl,
    __nv_bfloat16* __restrict__ th, __nv_bfloat16* __restrict__ tl,
    const float* __restrict__ gw, const float* __restrict__ be,
    const float* __restrict__ sumArr, const float* __restrict__ ssArr)
{
    __shared__ float tile[32][33];
    __shared__ float sc[32], sh[32];
    int t = threadIdx.x;
    int n0 = blockIdx.x * 32, c0 = blockIdx.y * 32;
    if (t < 32) {
        int c = c0 + t;
        float m = sumArr[c] * (1.f / NNODES);
        float var = ssArr[c] * (1.f / NNODES) - m * m;
        float s = gw[c] * rsqrtf(var + 1e-5f);
        sc[t] = s;
        sh[t] = be[c] - s * m;
    }
    __syncthreads();
    int nl = t >> 3, cg = t & 7;
    long long idx = (long long)(n0 + nl) * 128 + c0 + cg * 4;
    float4 v = *reinterpret_cast<const float4*>(y + idx);
    float o0, o1, o2, o3;
    {
        float a;
        a = sc[cg * 4 + 0] * v.x + sh[cg * 4 + 0]; o0 = a / (1.f + __expf(-a));
        a = sc[cg * 4 + 1] * v.y + sh[cg * 4 + 1]; o1 = a / (1.f + __expf(-a));
        a = sc[cg * 4 + 2] * v.z + sh[cg * 4 + 2]; o2 = a / (1.f + __expf(-a));
        a = sc[cg * 4 + 3] * v.w + sh[cg * 4 + 3]; o3 = a / (1.f + __expf(-a));
    }
    if (RES) {
        float4 r = *reinterpret_cast<const float4*>(res + idx);
        o0 += r.x; o1 += r.y; o2 += r.z; o3 += r.w;
    }
    if (WH) {
        float4 ov = { o0, o1, o2, o3 };
        *reinterpret_cast<float4*>(h + idx) = ov;
    }
    {
        uint2 hv, lv;
        hv.x = pack_hi(o0, o1); hv.y = pack_hi(o2, o3);
        lv.x = pack_lo(o0, o1); lv.y = pack_lo(o2, o3);
        *reinterpret_cast<uint2*>(rh + idx) = hv;
        *reinterpret_cast<uint2*>(rl + idx) = lv;
    }
    if (WT) {
        tile[nl][cg * 4 + 0] = o0; tile[nl][cg * 4 + 1] = o1;
        tile[nl][cg * 4 + 2] = o2; tile[nl][cg * 4 + 3] = o3;
        __syncthreads();
        int cc = t >> 3, g = t & 7;
        float w0 = tile[g * 4 + 0][cc], w1 = tile[g * 4 + 1][cc];
        float w2 = tile[g * 4 + 2][cc], w3 = tile[g * 4 + 3][cc];
        long long o = (long long)(c0 + cc) * NNODES + n0 + g * 4;
        uint2 hv, lv;
        hv.x = pack_hi(w0, w1); hv.y = pack_hi(w2, w3);
        lv.x = pack_lo(w0, w1); lv.y = pack_lo(w2, w3);
        *reinterpret_cast<uint2*>(th + o) = hv;
        *reinterpret_cast<uint2*>(tl + o) = lv;
    }
}

// ================= reduce partials + dinv2 + An; reset stack-2 state =================
__global__ __launch_bounds__(256) void k_reduce_an() {
    int b = blockIdx.x, t = threadIdx.x;
    if (b == 0 && t < 128) {
        g_s2a[t] = 0.f; g_q2a[t] = 0.f; g_s2b[t] = 0.f; g_q2b[t] = 0.f;
        if (t == 0) g_bar = 0;
    }
    const long long PS = (long long)NB * CH * CH;
    const long long BO = (long long)b * CH * CH;
    __shared__ float sd[128];
    for (int idx = t; idx < CH * CH; idx += 256) {
        float s = 0.f;
#pragma unroll
        for (int p = 0; p < 8; p++) s += g_xpart[p * PS + BO + idx];
        g_x2[BO + idx] = s;
    }
    int w = t >> 5, lane = t & 31;
    for (int r = w; r < 128; r += 8) {
        float rsum = 0.f;
#pragma unroll
        for (int q = 0; q < 4; q++) {
            int idx = r * 128 + lane + q * 32;
            float s = 0.f;
#pragma unroll
            for (int p = 0; p < 8; p++) s += g_apart[p * PS + BO + idx];
            g_A2[BO + idx] = s;
            rsum += s;
        }
#pragma unroll
        for (int o = 16; o; o >>= 1) rsum += __shfl_down_sync(0xffffffffu, rsum, o);
        if (lane == 0) sd[r] = rsqrtf(rsum + 1.0f);
    }
    __syncthreads();
    for (int idx = t; idx < CH * CH; idx += 256) {
        int i = idx >> 7, j = idx & 127;
        float v = g_A2[BO + idx] + (i == j ? 1.f : 0.f);
        g_An[BO + idx] = sd[i] * v * sd[j];
    }
}

// ================= fused stack-2 (32 blocks, grid barrier) =================
__device__ __forceinline__ void gridbar(int target) {
    __syncthreads();
    __threadfence();
    if (threadIdx.x == 0) {
        atomicAdd(&g_bar, 1);
        while (*(volatile int*)&g_bar < target) __nanosleep(64);
    }
    __syncthreads();
    __threadfence();
}

__device__ __forceinline__ void gemm_sm128(const float* __restrict__ P, const float* __restrict__ Q,
                                           unsigned long long acc2[8][4], int tx, int ty)
{
#pragma unroll
    for (int i = 0; i < 8; i++)
#pragma unroll
        for (int j = 0; j < 4; j++) acc2[i][j] = 0ull;
#pragma unroll 2
    for (int k = 0; k < 128; k++) {
        float a[8];
#pragma unroll
        for (int i = 0; i < 8; i++) a[i] = P[(ty * 8 + i) * 128 + k];
        const unsigned long long* Qp =
            reinterpret_cast<const unsigned long long*>(&Q[k * 128 + tx * 8]);
        unsigned long long b0 = Qp[0], b1 = Qp[1], b2 = Qp[2], b3 = Qp[3];
#pragma unroll
        for (int i = 0; i < 8; i++) {
            unsigned long long ad = dup_f32(a[i]);
            ffma2(acc2[i][0], ad, b0);
            ffma2(acc2[i][1], ad, b1);
            ffma2(acc2[i][2], ad, b2);
            ffma2(acc2[i][3], ad, b3);
        }
    }
}

__global__ __launch_bounds__(256) void k_stack2(
    const float* __restrict__ w2a, const float* __restrict__ b2a,
    const float* __restrict__ g2a, const float* __restrict__ be2a,
    const float* __restrict__ w2b, const float* __restrict__ b2b,
    const float* __restrict__ g2b, const float* __restrict__ be2b,
    const float* __restrict__ wl, const float* __restrict__ bl,
    float* __restrict__ out, int out_size)
{
    extern __shared__ __align__(16) float sm2[];
    float* AN = sm2;
    float* XB = sm2 + 16384;
    float* WB = sm2 + 32768;
    __shared__ float red[2048];
    __shared__ float gv[128];
    __shared__ float lg[10];
    __shared__ float lse;
    int b = blockIdx.x, t = threadIdx.x, tx = t & 15, ty = t >> 4;
    const float INVN = 1.f / (NB * CH);

    {
        const float4* pAn = (const float4*)(g_An + (long long)b * 16384);
        const float4* pX2 = (const float4*)(g_x2 + (long long)b * 16384);
        const float4* pWa = (const float4*)w2a;
        float4* An4 = (float4*)AN; float4* X4 = (float4*)XB; float4* W4 = (float4*)WB;
        for (int i = t; i < 4096; i += 256) { An4[i] = pAn[i]; X4[i] = pX2[i]; W4[i] = pWa[i]; }
    }
    __syncthreads();

    unsigned long long acc2[8][4];
    float cs[8], cq[8];

    gemm_sm128(XB, WB, acc2, tx, ty);
    __syncthreads();
#pragma unroll
    for (int i = 0; i < 8; i++)
#pragma unroll
        for (int j = 0; j < 4; j++) {
            float2 p = u2f(acc2[i][j]);
            XB[(ty * 8 + i) * 128 + tx * 8 + 2 * j] = p.x;
            XB[(ty * 8 + i) * 128 + tx * 8 + 2 * j + 1] = p.y;
        }
    __syncthreads();

    gemm_sm128(AN, XB, acc2, tx, ty);
    __syncthreads();
#pragma unroll
    for (int j = 0; j < 8; j++) { cs[j] = 0.f; cq[j] = 0.f; }
#pragma unroll
    for (int i = 0; i < 8; i++)
#pragma unroll
        for (int j = 0; j < 4; j++) {
            float2 p = u2f(acc2[i][j]);
            float v0 = p.x + b2a[tx * 8 + 2 * j];
            float v1 = p.y + b2a[tx * 8 + 2 * j + 1];
            WB[(ty * 8 + i) * 128 + tx * 8 + 2 * j] = v0;
            WB[(ty * 8 + i) * 128 + tx * 8 + 2 * j + 1] = v1;
            cs[2 * j] += v0; cq[2 * j] += v0 * v0;
            cs[2 * j + 1] += v1; cq[2 * j + 1] += v1 * v1;
        }
#pragma unroll
    for (int j = 0; j < 8; j++) red[ty * 128 + tx * 8 + j] = cs[j];
    __syncthreads();
    if (t < 128) { float s = 0.f; for (int g = 0; g < 16; g++) s += red[g * 128 + t]; atomicAdd(&g_s2a[t], s); }
    __syncthreads();
#pragma unroll
    for (int j = 0; j < 8; j++) red[ty * 128 + tx * 8 + j] = cq[j];
    __syncthreads();
    if (t < 128) { float s = 0.f; for (int g = 0; g < 16; g++) s += red[g * 128 + t]; atomicAdd(&g_q2a[t], s); }

    gridbar(NB);

    float scv[8], shv[8];
#pragma unroll
    for (int j = 0; j < 8; j++) {
        int c = tx * 8 + j;
        float m = g_s2a[c] * INVN;
        float var = g_q2a[c] * INVN - m * m;
        float s = g2a[c] * rsqrtf(var + 1e-5f);
        scv[j] = s; shv[j] = be2a[c] - s * m;
    }
#pragma unroll
    for (int i = 0; i < 8; i++)
#pragma unroll
        for (int j = 0; j < 8; j++) {
            float v = WB[(ty * 8 + i) * 128 + tx * 8 + j];
            v = scv[j] * v + shv[j];
            v = v / (1.f + __expf(-v));
            XB[(ty * 8 + i) * 128 + tx * 8 + j] = v;
        }
    __syncthreads();

    {
        const float4* pWb = (const float4*)w2b;
        float4* W4 = (float4*)WB;
        for (int i = t; i < 4096; i += 256) W4[i] = pWb[i];
    }
    __syncthreads();

    gemm_sm128(XB, WB, acc2, tx, ty);
    __syncthreads();
#pragma unroll
    for (int i = 0; i < 8; i++)
#pragma unroll
        for (int j = 0; j < 4; j++) {
            float2 p = u2f(acc2[i][j]);
            WB[(ty * 8 + i) * 128 + tx * 8 + 2 * j] = p.x;
            WB[(ty * 8 + i) * 128 + tx * 8 + 2 * j + 1] = p.y;
        }
    __syncthreads();

    gemm_sm128(AN, WB, acc2, tx, ty);
#pragma unroll
    for (int j = 0; j < 8; j++) { cs[j] = 0.f; cq[j] = 0.f; }
#pragma unroll
    for (int i = 0; i < 8; i++)
#pragma unroll
        for (int j = 0; j < 4; j++) {
            float2 p = u2f(acc2[i][j]);
            float v0 = p.x + b2b[tx * 8 + 2 * j];
            float v1 = p.y + b2b[tx * 8 + 2 * j + 1];
            cs[2 * j] += v0; cq[2 * j] += v0 * v0;
            cs[2 * j + 1] += v1; cq[2 * j + 1] += v1 * v1;
        }
    __syncthreads();
#pragma unroll
    for (int j = 0; j < 8; j++) red[ty * 128 + tx * 8 + j] = cs[j];
    __syncthreads();
    if (t < 128) { float s = 0.f; for (int g = 0; g < 16; g++) s += red[g * 128 + t]; atomicAdd(&g_s2b[t], s); }
    __syncthreads();
#pragma unroll
    for (int j = 0; j < 8; j++) red[ty * 128 + tx * 8 + j] = cq[j];
    __syncthreads();
    if (t < 128) { float s = 0.f; for (int g = 0; g < 16; g++) s += red[g * 128 + t]; atomicAdd(&g_q2b[t], s); }

    gridbar(2 * NB);

#pragma unroll
    for (int j = 0; j < 8; j++) {
        int c = tx * 8 + j;
        float m = g_s2b[c] * INVN;
        float var = g_q2b[c] * INVN - m * m;
        float s = g2b[c] * rsqrtf(var + 1e-5f);
        scv[j] = s; shv[j] = be2b[c] - s * m;
    }
    float colsum[8];
#pragma unroll
    for (int j = 0; j < 8; j++) colsum[j] = 0.f;
#pragma unroll
    for (int i = 0; i < 8; i++)
#pragma unroll
        for (int j = 0; j < 4; j++) {
            float2 p = u2f(acc2[i][j]);
            float v0 = scv[2 * j] * (p.x + b2b[tx * 8 + 2 * j]) + shv[2 * j];
            float v1 = scv[2 * j + 1] * (p.y + b2b[tx * 8 + 2 * j + 1]) + shv[2 * j + 1];
            v0 = v0 / (1.f + __expf(-v0));
            v1 = v1 / (1.f + __expf(-v1));
            v0 += XB[(ty * 8 + i) * 128 + tx * 8 + 2 * j];
            v1 += XB[(ty * 8 + i) * 128 + tx * 8 + 2 * j + 1];
            colsum[2 * j] += v0;
            colsum[2 * j + 1] += v1;
        }
    __syncthreads();
#pragma unroll
    for (int j = 0; j < 8; j++) red[ty * 128 + tx * 8 + j] = colsum[j];
    __syncthreads();
    if (t < 128) {
        float s = 0.f;
        for (int g = 0; g < 16; g++) s += red[g * 128 + t];
        gv[t] = s * (1.f / 32.f);
    }
    __syncthreads();
    if (t < 10) {
        float a = bl[t];
        for (int k = 0; k < 128; k++) a += gv[k] * wl[k * 10 + t];
        lg[t] = a;
    }
    __syncthreads();
    if (t == 0) {
        float mx = -1e30f;
        for (int j = 0; j < 10; j++) mx = fmaxf(mx, lg[j]);
        float se = 0.f;
        for (int j = 0; j < 10; j++) se += expf(lg[j] - mx);
        lse = mx + logf(se);
    }
    __syncthreads();
    if (t < 10) {
        int o = b * 10 + t;
        if (o < out_size) out[o] = lg[t] - lse;
    }
    if (b == 0) {
        for (int idx = NB * 10 + t; idx < out_size; idx += 256) out[idx] = 0.f;
    }
}

// ================= host orchestration =================
extern "C" void kernel_launch(void* const* d_in, const int* in_sizes, int n_in,
                              void* d_out, int out_size) {
    const float* x    = (const float*)d_in[0];
    const int*   ei   = (const int*)  d_in[1];
    const float* w1a  = (const float*)d_in[4];
    const float* b1a  = (const float*)d_in[5];
    const float* g1a  = (const float*)d_in[6];
    const float* be1a = (const float*)d_in[7];
    const float* w1b  = (const float*)d_in[8];
    const float* b1b  = (const float*)d_in[9];
    const float* g1b  = (const float*)d_in[10];
    const float* be1b = (const float*)d_in[11];
    const float* wp1  = (const float*)d_in[12];
    const float* bp1  = (const float*)d_in[13];
    const float* w2a  = (const float*)d_in[14];
    const float* b2a  = (const float*)d_in[15];
    const float* g2a  = (const float*)d_in[16];
    const float* be2a = (const float*)d_in[17];
    const float* w2b  = (const float*)d_in[18];
    const float* b2b  = (const float*)d_in[19];
    const float* g2b  = (const float*)d_in[20];
    const float* be2b = (const float*)d_in[21];
    const float* wl   = (const float*)d_in[24];
    const float* bl   = (const float*)d_in[25];
    float* outp = (float*)d_out;
    (void)n_in; (void)in_sizes;

    float *p_lin, *p_y, *p_h, *p_s, *p_xpart, *p_apart;
    float *p_sumA, *p_ssA, *p_sumB, *p_ssB;
    __nv_bfloat16 *p_axh, *p_axl, *p_hah, *p_hal, *p_hbh, *p_hbl;
    __nv_bfloat16 *p_hTh, *p_hTl, *p_sTh, *p_sTl, *p_tTh, *p_tTl;
    __nv_bfloat16 *p_w1ah, *p_w1al, *p_w1bh, *p_w1bl, *p_wp1h, *p_wp1l;
    cudaGetSymbolAddress((void**)&p_lin,   g_lin);
    cudaGetSymbolAddress((void**)&p_y,     g_y);
    cudaGetSymbolAddress((void**)&p_h,     g_h);
    cudaGetSymbolAddress((void**)&p_s,     g_s);
    cudaGetSymbolAddress((void**)&p_xpart, g_xpart);
    cudaGetSymbolAddress((void**)&p_apart, g_apart);
    cudaGetSymbolAddress((void**)&p_sumA,  g_sumA);
    cudaGetSymbolAddress((void**)&p_ssA,   g_ssA);
    cudaGetSymbolAddress((void**)&p_sumB,  g_sumB);
    cudaGetSymbolAddress((void**)&p_ssB,   g_ssB);
    cudaGetSymbolAddress((void**)&p_axh,   g_axh);
    cudaGetSymbolAddress((void**)&p_axl,   g_axl);
    cudaGetSymbolAddress((void**)&p_hah,   g_hah);
    cudaGetSymbolAddress((void**)&p_hal,   g_hal);
    cudaGetSymbolAddress((void**)&p_hbh,   g_hbh);
    cudaGetSymbolAddress((void**)&p_hbl,   g_hbl);
    cudaGetSymbolAddress((void**)&p_hTh,   g_hTh);
    cudaGetSymbolAddress((void**)&p_hTl,   g_hTl);
    cudaGetSymbolAddress((void**)&p_sTh,   g_sTh);
    cudaGetSymbolAddress((void**)&p_sTl,   g_sTl);
    cudaGetSymbolAddress((void**)&p_tTh,   g_tTh);
    cudaGetSymbolAddress((void**)&p_tTl,   g_tTl);
    cudaGetSymbolAddress((void**)&p_w1ah,  g_w1ah);
    cudaGetSymbolAddress((void**)&p_w1al,  g_w1al);
    cudaGetSymbolAddress((void**)&p_w1bh,  g_w1bh);
    cudaGetSymbolAddress((void**)&p_w1bl,  g_w1bl);
    cudaGetSymbolAddress((void**)&p_wp1h,  g_wp1h);
    cudaGetSymbolAddress((void**)&p_wp1l,  g_wp1l);

    static bool attrDone = false;
    if (!attrDone) {
        cudaFuncSetAttribute(k_stack2, cudaFuncAttributeMaxDynamicSharedMemorySize, 196608);
        cudaFuncSetAttribute(k_mma<false, true>,  cudaFuncAttributeMaxDynamicSharedMemorySize, 50176);
        cudaFuncSetAttribute(k_mma<false, false>, cudaFuncAttributeMaxDynamicSharedMemorySize, 50176);
        cudaFuncSetAttribute(k_mma<true, false>,  cudaFuncAttributeMaxDynamicSharedMemorySize, 50176);
        attrDone = true;
    }

    // graph structure
    k_zero_deg<<<NNODES / 256, 256>>>();
    k_deg  <<<NEDGES / 256, 256>>>(ei);
    k_alloc<<<NNODES / 1024, 1024>>>();
    k_fill <<<NEDGES / 256, 256>>>(ei);
    k_wsplit<<<160, 256>>>(w1a, w1b, wp1);

    // stack 1, layer a: agg(x) -> bf16 -> mma GEMM (K=64, bias+stats)
    k_aggx<<<NNODES / 8, 256>>>(x);
    k_mma<false, true><<<256, 256, 50176>>>(p_axh, p_axl, 64,
                                            p_w1ah, p_w1al, nullptr, nullptr, 64,
                                            b1a, p_y, nullptr, 64);
    k_bn<false, true, false><<<dim3(NNODES / 32, 4), 256>>>(
        p_y, nullptr, p_h, p_hah, p_hal, nullptr, nullptr, g1a, be1a, p_sumA, p_ssA);

    // stack 1, layer b (residual)
    k_mma<false, false><<<256, 256, 50176>>>(p_hah, p_hal, 128,
                                             p_w1bh, p_w1bl, nullptr, nullptr, 128,
                                             nullptr, p_lin, nullptr, 128);
    k_aggw<0><<<NNODES / 8, 256>>>(p_lin, b1b, p_y, nullptr, nullptr);
    k_bn<true, false, true><<<dim3(NNODES / 32, 4), 256>>>(
        p_y, p_h, nullptr, p_hbh, p_hbl, p_hTh, p_hTl, g1b, be1b, p_sumB, p_ssB);

    // pooling 1: lin = h @ wp1; s = softmax(agg(lin)+bp1); t = A s
    k_mma<false, false><<<256, 256, 50176>>>(p_hbh, p_hbl, 128,
                                             p_wp1h, p_wp1l, nullptr, nullptr, 128,
                                             nullptr, p_lin, nullptr, 128);
    k_aggw<1><<<NNODES / 8, 256>>>(p_lin, bp1, p_s, p_sTh, p_sTl);
    k_aggw<2><<<NNODES / 8, 256>>>(p_s, nullptr, nullptr, p_tTh, p_tTl);

    // pooled einsums: x2 = s^T h, A2 = s^T t (8-way K-split partials)
    k_mma<true, false><<<dim3(1, 16, NB), 256, 50176>>>(p_sTh, p_sTl, NNODES,
                                                        p_hTh, p_hTl, p_tTh, p_tTl, NNODES,
                                                        nullptr, p_xpart, p_apart, 128);
    k_reduce_an<<<NB, 256>>>();

    // fused stack 2 + head
    k_stack2<<<NB, 256, 196608>>>(w2a, b2a, g2a, be2a, w2b, b2b, g2b, be2b, wl, bl, outp, out_size);
}